// round 15
// baseline (speedup 1.0000x reference)
#include <cuda_runtime.h>
#include <cuda_bf16.h>
#include <math.h>
#include <stdint.h>

#define NN 100000
#define KK 20
#define DD 96
#define HH 1024
#define CC 7
#define KPAD 100096
#define GSPLIT 4
#define NTRI 36
#define NCHUNK 32
#define NBLK 391
#define NB 32                      // persistent-kernel block count

// gram smem geometry
#define GS_ROWB 144
#define GS_TILE (128 * GS_ROWB)
#define GS_STAGE (4 * GS_TILE)
#define GS_TOTAL (2 * GS_STAGE)

// ---------------- scratch ----------------
static __device__ int           d_preds[NN];
static __device__ float         d_maskf[NN];
static __device__ int           d_bcnt[NBLK];
static __device__ int           d_boff[NBLK];
static __device__ int           d_nact;
static __device__ int           d_nchunk;
static __device__ int           d_active[NN];
static __device__ float         d_featH[(long long)NN * HH];
static __device__ __nv_bfloat16 d_Fhi[(long long)HH * KPAD];
static __device__ __nv_bfloat16 d_Flo[(long long)HH * KPAD];
static __device__ float         d_Spart[GSPLIT * NTRI * 128 * 128];
static __device__ float         d_Qpart[NCHUNK * HH * CC];
static __device__ float         d_Qn[HH * CC];
static __device__ float         d_Gn[HH * HH];
static __device__ float         d_GA[HH * HH];
static __device__ float         d_Gf[HH * HH];
static __device__ float         d_dinvf[HH];
static __device__ float         d_res[HH * CC];
static __device__ float         d_wo[HH * CC];
static __device__ unsigned int  g_cnt = 0;
static __device__ unsigned int  g_gen = 0;

// ---------------- ptx helpers ----------------
__device__ __forceinline__ uint32_t smem_to_u32(const void* smem_ptr) {
    uint32_t addr;
    asm("{ .reg .u64 tmp; cvta.to.shared.u64 tmp, %1; cvt.u32.u64 %0, tmp; }"
        : "=r"(addr) : "l"(smem_ptr));
    return addr;
}
#define CP_ASYNC16(dst, src) \
    asm volatile("cp.async.cg.shared.global [%0], [%1], 16;" :: "r"(dst), "l"(src))
#define CP_COMMIT() asm volatile("cp.async.commit_group;" ::: "memory")
#define CP_WAIT1()  asm volatile("cp.async.wait_group 1;" ::: "memory")
#define CP_WAIT0()  asm volatile("cp.async.wait_group 0;" ::: "memory")
#define LDSM4(r, addr) \
    asm volatile("ldmatrix.sync.aligned.m8n8.x4.shared.b16 {%0,%1,%2,%3}, [%4];" \
        : "=r"((r)[0]), "=r"((r)[1]), "=r"((r)[2]), "=r"((r)[3]) : "r"(addr))
#define MMA16816(c, a, b) \
    asm volatile("mma.sync.aligned.m16n8k16.row.col.f32.bf16.bf16.f32 " \
        "{%0,%1,%2,%3}, {%4,%5,%6,%7}, {%8,%9}, {%0,%1,%2,%3};" \
        : "+f"((c)[0]), "+f"((c)[1]), "+f"((c)[2]), "+f"((c)[3]) \
        : "r"((a)[0]), "r"((a)[1]), "r"((a)[2]), "r"((a)[3]), "r"((b)[0]), "r"((b)[1]))

__device__ __forceinline__ unsigned long long ffma2(unsigned long long a,
                                                    unsigned long long b,
                                                    unsigned long long c) {
    unsigned long long d;
    asm("fma.rn.f32x2 %0, %1, %2, %3;" : "=l"(d) : "l"(a), "l"(b), "l"(c));
    return d;
}
__device__ __forceinline__ unsigned long long dup2(float x) {
    unsigned long long d;
    asm("mov.b64 %0, {%1, %1};" : "=l"(d) : "f"(x));
    return d;
}
__device__ __forceinline__ float2 up2(unsigned long long v) {
    float2 r;
    asm("mov.b64 {%0, %1}, %2;" : "=f"(r.x), "=f"(r.y) : "l"(v));
    return r;
}
__device__ __forceinline__ unsigned long long d2u(double d) {
    return (unsigned long long)__double_as_longlong(d);
}

// ---------------- preds ----------------
__global__ __launch_bounds__(256) void preds_kernel(const float* __restrict__ feat,
                                                    const float* __restrict__ proto) {
    __shared__ float sp[CC][DD];
    int tid = threadIdx.x;
    if (tid < CC) {
        float s = 0.f;
        for (int k = 0; k < DD; k++) { float v = proto[tid * DD + k]; s += v * v; }
        float inv = 1.f / fmaxf(sqrtf(s), 1e-12f);
        for (int k = 0; k < DD; k++) sp[tid][k] = proto[tid * DD + k] * inv;
    }
    __syncthreads();
    int n = blockIdx.x * 256 + tid;
    if (n >= NN) return;
    const float* f = feat + (long long)n * DD;
    float acc[CC];
#pragma unroll
    for (int c = 0; c < CC; c++) acc[c] = 0.f;
#pragma unroll 4
    for (int k = 0; k < DD; k++) {
        float fk = f[k];
#pragma unroll
        for (int c = 0; c < CC; c++) acc[c] += fk * sp[c][k];
    }
    float best = acc[0];
    int bi = 0;
#pragma unroll
    for (int c = 1; c < CC; c++)
        if (acc[c] > best) { best = acc[c]; bi = c; }
    d_preds[n] = bi;
}

// ---------------- mask + per-block count ----------------
__global__ __launch_bounds__(256) void mask_kernel(const float* __restrict__ coords,
                                                   const float* __restrict__ normz,
                                                   const void* __restrict__ nidx) {
    __shared__ int wsum[8];
    int tid = threadIdx.x;
    int n = blockIdx.x * 256 + tid;
    bool mk = false;
    if (n < NN) {
        const int* pw = (const int*)nidx;
        int is64 = 1;
#pragma unroll
        for (int k = 1; k < 40; k += 2) is64 &= (pw[k] == 0);
        int p = d_preds[n];
        const long long* ni64 = (const long long*)nidx;
        const int*       ni32 = (const int*)nidx;
        int cnt = 0;
#pragma unroll
        for (int k = 0; k < KK; k++) {
            long long raw = is64 ? ni64[(long long)n * KK + k]
                                 : (long long)ni32[(long long)n * KK + k];
            unsigned int idx = (unsigned int)raw;
            if (idx >= NN) idx = 0;
            cnt += (d_preds[idx] == p);
        }
        bool cmask = cnt > 16;
        bool plane   = (p == 2) | (p == 3) | (p == 4);
        bool manmade = (p == 5);
        bool other   = (p == 0) | (p == 1) | (p == 6);
        float nz = normz[n];
        float z  = coords[(long long)n * 3 + 2];
        bool ground = plane && (nz > 0.9f) && (z < -10.0f);
        bool g = ground || other || manmade;
        bool m = (manmade && (nz < 0.1f)) || other || plane;
        mk = cmask && g && m;
        d_maskf[n] = mk ? 1.f : 0.f;
    }
    unsigned int b = __ballot_sync(0xffffffffu, mk);
    if ((tid & 31) == 0) wsum[tid >> 5] = __popc(b);
    __syncthreads();
    if (tid == 0) {
        int s = 0;
#pragma unroll
        for (int w = 0; w < 8; w++) s += wsum[w];
        d_bcnt[blockIdx.x] = s;
    }
}

// ---------------- scan ----------------
__global__ __launch_bounds__(512) void scan_kernel() {
    __shared__ int s[NBLK];
    int tid = threadIdx.x;
    if (tid < NBLK) s[tid] = d_bcnt[tid];
    __syncthreads();
    if (tid == 0) {
        int run = 0;
        for (int i = 0; i < NBLK; i++) { int v = s[i]; s[i] = run; run += v; }
        d_nact = run;
        d_nchunk = (run + 63) / 64;
    }
    __syncthreads();
    if (tid < NBLK) d_boff[tid] = s[tid];
}

// ---------------- scatter ----------------
__global__ __launch_bounds__(256) void scatter_kernel() {
    __shared__ int wcnt[8];
    __shared__ int woff[8];
    int tid = threadIdx.x;
    int n = blockIdx.x * 256 + tid;
    bool mk = (n < NN) && (d_maskf[n] != 0.f);
    unsigned int b = __ballot_sync(0xffffffffu, mk);
    int lane = tid & 31, wid = tid >> 5;
    if (lane == 0) wcnt[wid] = __popc(b);
    __syncthreads();
    if (tid == 0) {
        int run = 0;
#pragma unroll
        for (int w = 0; w < 8; w++) { woff[w] = run; run += wcnt[w]; }
    }
    __syncthreads();
    if (mk) {
        int rank = __popc(b & ((1u << lane) - 1u));
        d_active[d_boff[blockIdx.x] + woff[wid] + rank] = n;
    }
}

// ---------------- feath (fp32 only) ----------------
__global__ __launch_bounds__(256) void feath_kernel(const float* __restrict__ feat,
                                                    const float* __restrict__ w) {
    __shared__ __align__(16) float As[32][68];
    __shared__ __align__(16) float Bs[32][68];
    int tid = threadIdx.x;
    int h0 = blockIdx.x * 64;
    int n0 = blockIdx.y * 64;
    int tx = tid & 15, ty = tid >> 4;
    unsigned long long acc[4][2];
#pragma unroll
    for (int r = 0; r < 4; r++) { acc[r][0] = 0ull; acc[r][1] = 0ull; }

    for (int k0 = 0; k0 < DD; k0 += 32) {
        for (int i = tid; i < 64 * 32; i += 256) {
            int k = i & 31, m = i >> 5;
            int n = n0 + m;
            As[k][m] = (n < NN) ? feat[(long long)n * DD + k0 + k] : 0.f;
        }
        for (int i = tid; i < 32 * 64; i += 256) {
            int k = i >> 6, m = i & 63;
            Bs[k][m] = w[(k0 + k) * HH + h0 + m];
        }
        __syncthreads();
#pragma unroll
        for (int k = 0; k < 32; k++) {
            float4 a = *reinterpret_cast<const float4*>(&As[k][ty << 2]);
            double2 bd = *reinterpret_cast<const double2*>(&Bs[k][tx << 2]);
            unsigned long long b0 = d2u(bd.x), b1 = d2u(bd.y);
            unsigned long long a0 = dup2(a.x), a1 = dup2(a.y), a2 = dup2(a.z), a3 = dup2(a.w);
            acc[0][0] = ffma2(a0, b0, acc[0][0]); acc[0][1] = ffma2(a0, b1, acc[0][1]);
            acc[1][0] = ffma2(a1, b0, acc[1][0]); acc[1][1] = ffma2(a1, b1, acc[1][1]);
            acc[2][0] = ffma2(a2, b0, acc[2][0]); acc[2][1] = ffma2(a2, b1, acc[2][1]);
            acc[3][0] = ffma2(a3, b0, acc[3][0]); acc[3][1] = ffma2(a3, b1, acc[3][1]);
        }
        __syncthreads();
    }
#pragma unroll
    for (int r = 0; r < 4; r++) {
        int n = n0 + (ty << 2) + r;
        if (n < NN) {
            float2 v0 = up2(acc[r][0]);
            float2 v1 = up2(acc[r][1]);
            *reinterpret_cast<float4*>(&d_featH[(long long)n * HH + h0 + (tx << 2)]) =
                make_float4(fmaxf(v0.x, 0.f), fmaxf(v0.y, 0.f),
                            fmaxf(v1.x, 0.f), fmaxf(v1.y, 0.f));
        }
    }
}

// ---------------- compact ----------------
__global__ __launch_bounds__(256) void compact_kernel() {
    __shared__ float sT[64][65];
    int tid = threadIdx.x;
    int h0 = blockIdx.x * 64;
    int NCH = d_nchunk;
    int nact = d_nact;
    for (int cb = blockIdx.y; cb < NCH; cb += 64) {
        int p0 = cb * 64;
        int pl = tid >> 2, seg = tid & 3;
        int p = p0 + pl;
        int n = (p < nact) ? d_active[p] : -1;
        float4 v0, v1, v2, v3;
        if (n >= 0) {
            const float* src = &d_featH[(long long)n * HH + h0 + seg * 16];
            v0 = *reinterpret_cast<const float4*>(src);
            v1 = *reinterpret_cast<const float4*>(src + 4);
            v2 = *reinterpret_cast<const float4*>(src + 8);
            v3 = *reinterpret_cast<const float4*>(src + 12);
        } else {
            v0 = v1 = v2 = v3 = make_float4(0.f, 0.f, 0.f, 0.f);
        }
        __syncthreads();
        {
            int hb = seg * 16;
            sT[hb + 0][pl] = v0.x;  sT[hb + 1][pl] = v0.y;
            sT[hb + 2][pl] = v0.z;  sT[hb + 3][pl] = v0.w;
            sT[hb + 4][pl] = v1.x;  sT[hb + 5][pl] = v1.y;
            sT[hb + 6][pl] = v1.z;  sT[hb + 7][pl] = v1.w;
            sT[hb + 8][pl] = v2.x;  sT[hb + 9][pl] = v2.y;
            sT[hb + 10][pl] = v2.z; sT[hb + 11][pl] = v2.w;
            sT[hb + 12][pl] = v3.x; sT[hb + 13][pl] = v3.y;
            sT[hb + 14][pl] = v3.z; sT[hb + 15][pl] = v3.w;
        }
        __syncthreads();
        {
            int hrow = tid >> 2, q = tid & 3;
            __align__(16) __nv_bfloat16 hb16[16], lb16[16];
#pragma unroll
            for (int i = 0; i < 16; i++) {
                float v = sT[hrow][q * 16 + i];
                __nv_bfloat16 h = __float2bfloat16(v);
                hb16[i] = h;
                lb16[i] = __float2bfloat16(v - __bfloat162float(h));
            }
            size_t gb = (size_t)(h0 + hrow) * KPAD + p0 + q * 16;
            *reinterpret_cast<uint4*>(&d_Fhi[gb])     = *reinterpret_cast<uint4*>(&hb16[0]);
            *reinterpret_cast<uint4*>(&d_Fhi[gb + 8]) = *reinterpret_cast<uint4*>(&hb16[8]);
            *reinterpret_cast<uint4*>(&d_Flo[gb])     = *reinterpret_cast<uint4*>(&lb16[0]);
            *reinterpret_cast<uint4*>(&d_Flo[gb + 8]) = *reinterpret_cast<uint4*>(&lb16[8]);
        }
    }
}

// ---------------- Gram (dynamic chunk count) ----------------
__global__ __launch_bounds__(1024, 1) void gram_hmma_kernel() {
    extern __shared__ __align__(16) char smg[];
    uint32_t sb = smem_to_u32(smg);
    int tid = threadIdx.x;
    int t = blockIdx.x, sp = blockIdx.y;
    int bi = 0;
    while ((bi + 1) * (bi + 2) / 2 <= t) bi++;
    int bj = t - bi * (bi + 1) / 2;
    int h10 = bi * 128, h20 = bj * 128;

    int NCH = d_nchunk;
    int cps = (NCH + GSPLIT - 1) / GSPLIT;
    int c0 = sp * cps;
    int cnt = min(c0 + cps, NCH) - c0;
    float* out = &d_Spart[(size_t)(sp * NTRI + t) * 128 * 128];

    if (cnt <= 0) {
        float4 z = make_float4(0.f, 0.f, 0.f, 0.f);
        for (int i = tid; i < 128 * 128 / 4; i += 1024)
            *reinterpret_cast<float4*>(&out[i * 4]) = z;
        return;
    }

    int lrow = tid >> 3, lseg = tid & 7;
    size_t kstart = (size_t)c0 * 64 + lseg * 8;
    const __nv_bfloat16* pAh = d_Fhi + (size_t)(h10 + lrow) * KPAD + kstart;
    const __nv_bfloat16* pAl = d_Flo + (size_t)(h10 + lrow) * KPAD + kstart;
    const __nv_bfloat16* pBh = d_Fhi + (size_t)(h20 + lrow) * KPAD + kstart;
    const __nv_bfloat16* pBl = d_Flo + (size_t)(h20 + lrow) * KPAD + kstart;
    uint32_t ldst = sb + lrow * GS_ROWB + lseg * 16;

    int wid = tid >> 5, lane = tid & 31;
    int mbase = (wid >> 2) * 16, nbase = (wid & 3) * 32;
    int arow = (lane & 7) + ((lane >> 3) & 1) * 8;
    int acol = ((lane >> 4) & 1) * 8;
    int brow = (lane & 7) + ((lane >> 4) & 1) * 8;
    int bcol = ((lane >> 3) & 1) * 8;
    uint32_t aoff = (uint32_t)(((mbase + arow) * 72 + acol) * 2);
    uint32_t boff[2];
#pragma unroll
    for (int nj = 0; nj < 2; nj++)
        boff[nj] = (uint32_t)(((nbase + nj * 16 + brow) * 72 + bcol) * 2);

    float acc[4][4];
#pragma unroll
    for (int b = 0; b < 4; b++)
#pragma unroll
        for (int c = 0; c < 4; c++) acc[b][c] = 0.f;

    CP_ASYNC16(ldst + 0 * GS_TILE, pAh);
    CP_ASYNC16(ldst + 1 * GS_TILE, pAl);
    CP_ASYNC16(ldst + 2 * GS_TILE, pBh);
    CP_ASYNC16(ldst + 3 * GS_TILE, pBl);
    CP_COMMIT();

    for (int c = 0; c < cnt; c++) {
        if (c + 1 < cnt) {
            uint32_t base = ldst + ((c + 1) & 1) * GS_STAGE;
            size_t ko = (size_t)(c + 1) * 64;
            CP_ASYNC16(base + 0 * GS_TILE, pAh + ko);
            CP_ASYNC16(base + 1 * GS_TILE, pAl + ko);
            CP_ASYNC16(base + 2 * GS_TILE, pBh + ko);
            CP_ASYNC16(base + 3 * GS_TILE, pBl + ko);
            CP_COMMIT();
            CP_WAIT1();
        } else {
            CP_WAIT0();
        }
        __syncthreads();
        uint32_t stg = sb + (c & 1) * GS_STAGE;
#pragma unroll
        for (int ks = 0; ks < 4; ks++) {
            uint32_t kb = ks * 32;
            uint32_t ah[4], al[4], bh[4][2], bl[4][2];
            LDSM4(ah, stg + 0 * GS_TILE + aoff + kb);
#pragma unroll
            for (int nj = 0; nj < 2; nj++) {
                uint32_t r[4];
                LDSM4(r, stg + 2 * GS_TILE + boff[nj] + kb);
                bh[nj * 2][0] = r[0]; bh[nj * 2][1] = r[1];
                bh[nj * 2 + 1][0] = r[2]; bh[nj * 2 + 1][1] = r[3];
            }
#pragma unroll
            for (int nj = 0; nj < 4; nj++) MMA16816(acc[nj], ah, bh[nj]);
#pragma unroll
            for (int nj = 0; nj < 2; nj++) {
                uint32_t r[4];
                LDSM4(r, stg + 3 * GS_TILE + boff[nj] + kb);
                bl[nj * 2][0] = r[0]; bl[nj * 2][1] = r[1];
                bl[nj * 2 + 1][0] = r[2]; bl[nj * 2 + 1][1] = r[3];
            }
#pragma unroll
            for (int nj = 0; nj < 4; nj++) MMA16816(acc[nj], ah, bl[nj]);
            LDSM4(al, stg + 1 * GS_TILE + aoff + kb);
#pragma unroll
            for (int nj = 0; nj < 4; nj++) MMA16816(acc[nj], al, bh[nj]);
        }
        __syncthreads();
    }

    int g = lane >> 2, q = lane & 3;
#pragma unroll
    for (int nj = 0; nj < 4; nj++) {
        int r0 = mbase + g;
        int cc = nbase + nj * 8 + q * 2;
        *reinterpret_cast<float2*>(&out[r0 * 128 + cc]) =
            make_float2(acc[nj][0], acc[nj][1]);
        *reinterpret_cast<float2*>(&out[(r0 + 8) * 128 + cc]) =
            make_float2(acc[nj][2], acc[nj][3]);
    }
}

// ---------------- reduce split-K partials ----------------
__global__ __launch_bounds__(256) void greduce_kernel() {
    int t = blockIdx.x;
    int bi = 0;
    while ((bi + 1) * (bi + 2) / 2 <= t) bi++;
    int bj = t - bi * (bi + 1) / 2;
    for (int i = threadIdx.x; i < 128 * 128 / 4; i += 256) {
        float4 s = make_float4(0.f, 0.f, 0.f, 0.f);
#pragma unroll
        for (int sp = 0; sp < GSPLIT; sp++) {
            float4 v = *reinterpret_cast<const float4*>(
                &d_Spart[(size_t)(sp * NTRI + t) * 128 * 128 + i * 4]);
            s.x += v.x; s.y += v.y; s.z += v.z; s.w += v.w;
        }
        int r = (i * 4) >> 7, c = (i * 4) & 127;
        *reinterpret_cast<float4*>(&d_Gn[(bi * 128 + r) * HH + bj * 128 + c]) = s;
    }
}

// ---------------- Qn partials over active list ----------------
__global__ __launch_bounds__(256) void qpart_kernel() {
    int h = blockIdx.x * 256 + threadIdx.x;
    int chunk = blockIdx.y;
    int nact = d_nact;
    int stride = (nact + NCHUNK - 1) / NCHUNK;
    int p0 = chunk * stride;
    int p1 = min(p0 + stride, nact);
    float a0 = 0, a1 = 0, a2 = 0, a3 = 0, a4 = 0, a5 = 0, a6 = 0;
    for (int p = p0; p < p1; p++) {
        int n = d_active[p];
        float v = d_featH[(long long)n * HH + h];
        int pr = d_preds[n];
        a0 += (pr == 0) ? v : 0.f;
        a1 += (pr == 1) ? v : 0.f;
        a2 += (pr == 2) ? v : 0.f;
        a3 += (pr == 3) ? v : 0.f;
        a4 += (pr == 4) ? v : 0.f;
        a5 += (pr == 5) ? v : 0.f;
        a6 += (pr == 6) ? v : 0.f;
    }
    int o = (chunk * HH + h) * CC;
    d_Qpart[o + 0] = a0; d_Qpart[o + 1] = a1; d_Qpart[o + 2] = a2; d_Qpart[o + 3] = a3;
    d_Qpart[o + 4] = a4; d_Qpart[o + 5] = a5; d_Qpart[o + 6] = a6;
}

__global__ void qreduce_kernel(const float* __restrict__ Qin) {
    int idx = blockIdx.x * 256 + threadIdx.x;
    if (idx >= HH * CC) return;
    float s = Qin[idx];
    for (int ch = 0; ch < NCHUNK; ch++) s += d_Qpart[ch * HH * CC + idx];
    d_Qn[idx] = s;
}

// ---------------- mirror + Gin + ridge ----------------
__global__ void convm_kernel(const float* __restrict__ Gin) {
    int idx = blockIdx.x * 256 + threadIdx.x;
    int i = idx >> 10, j = idx & 1023;
    float v = (i >= j) ? d_Gn[i * HH + j] : d_Gn[j * HH + i];
    float a = v + Gin[idx] + ((i == j) ? 100.0f : 0.0f);
    d_GA[idx] = a;
    d_Gf[idx] = a;
}

// ================= fused Cholesky + solves (single persistent kernel) =================
__device__ __forceinline__ void gbar() {
    __threadfence();
    __syncthreads();
    if (threadIdx.x == 0) {
        unsigned int gen = atomicAdd(&g_gen, 0u);
        if (atomicAdd(&g_cnt, 1u) == NB - 1) {
            atomicExch(&g_cnt, 0u);
            __threadfence();
            atomicAdd(&g_gen, 1u);
        } else {
            while (atomicAdd(&g_gen, 0u) == gen) { __nanosleep(64); }
        }
        __threadfence();
    }
    __syncthreads();
}

__global__ __launch_bounds__(1024, 1) void chol_fused() {
    __shared__ union {
        float potf[64][65];
        struct { float L[64][65]; float di[64]; } trs;
        struct { float Li[64][65]; float Lj[64][65]; } syr;
        float sw[HH * CC];
    } u;
    __shared__ float shy[64][CC];

    int tid = threadIdx.x;
    int bid = blockIdx.x;
    int lane = tid & 31, wid = tid >> 5;

    // ---------- factorization ----------
    for (int kb = 0; kb < HH / 64; kb++) {
        int off = kb * 64;
        // phase A: potf2 by block 0
        if (bid == 0) {
            int i = tid;
            if (i < 64)
                for (int j = 0; j < 64; j++) u.potf[i][j] = d_Gf[(off + i) * HH + off + j];
            __syncthreads();
            for (int j = 0; j < 64; j++) {
                if (i == j) u.potf[j][j] = sqrtf(fmaxf(u.potf[j][j], 1e-20f));
                __syncthreads();
                if (i < 64 && i > j) u.potf[i][j] /= u.potf[j][j];
                __syncthreads();
                if (i < 64 && i > j) {
                    float lij = u.potf[i][j];
                    for (int k = j + 1; k <= i; k++) u.potf[i][k] -= lij * u.potf[k][j];
                }
                __syncthreads();
            }
            if (i < 64) {
                for (int j = 0; j <= i; j++) d_Gf[(off + i) * HH + off + j] = u.potf[i][j];
                d_dinvf[off + i] = 1.0f / u.potf[i][i];
            }
            __syncthreads();
        }
        gbar();

        int base = off + 64;
        int rows = HH - base;
        if (rows > 0) {
            // phase B: trsm, warp-per-row (lane owns cols 2l, 2l+1)
            for (int i = tid; i < 64 * 64; i += 1024)
                u.trs.L[i >> 6][i & 63] = d_Gf[(off + (i >> 6)) * HH + off + (i & 63)];
            if (tid < 64) u.trs.di[tid] = d_dinvf[off + tid];
            __syncthreads();
            int gw = bid * 32 + wid;       // 0..1023
            if (gw < rows) {
                int r = base + gw;
                float* a = &d_Gf[r * HH + off];
                int c0 = lane * 2, c1 = c0 + 1;
                float x0 = a[c0], x1 = a[c1];
#pragma unroll
                for (int j = 0; j < 64; j++) {
                    int owner = j >> 1;
                    float xo = ((j & 1) ? x1 : x0) * u.trs.di[j];
                    float xj = __shfl_sync(0xffffffffu, xo, owner);
                    if (lane == owner) { if (j & 1) x1 = xj; else x0 = xj; }
                    if (c0 > j) x0 -= xj * u.trs.L[c0][j];
                    if (c1 > j) x1 -= xj * u.trs.L[c1][j];
                }
                a[c0] = x0; a[c1] = x1;
            }
            gbar();

            // phase C: syrk, 64x64 lower tiles distributed across blocks
            int T = rows / 64;
            int ntiles = T * (T + 1) / 2;
            for (int idx = bid; idx < ntiles; idx += NB) {
                int ti = 0;
                while ((ti + 1) * (ti + 2) / 2 <= idx) ti++;
                int tj = idx - ti * (ti + 1) / 2;
                int i0 = base + ti * 64, j0 = base + tj * 64;
                __syncthreads();
                for (int i = tid; i < 64 * 64; i += 1024) {
                    u.syr.Li[i >> 6][i & 63] = d_Gf[(i0 + (i >> 6)) * HH + off + (i & 63)];
                    u.syr.Lj[i >> 6][i & 63] = d_Gf[(j0 + (i >> 6)) * HH + off + (i & 63)];
                }
                __syncthreads();
                int tx = tid & 63, tg = tid >> 6;   // tg 0..15
                float acc[4] = {0.f, 0.f, 0.f, 0.f};
                for (int t = 0; t < 64; t++) {
                    float bj = u.syr.Lj[tx][t];
#pragma unroll
                    for (int s = 0; s < 4; s++) acc[s] += u.syr.Li[tg + s * 16][t] * bj;
                }
#pragma unroll
                for (int s = 0; s < 4; s++)
                    d_Gf[(i0 + tg + s * 16) * HH + j0 + tx] -= acc[s];
            }
            gbar();
        } else {
            gbar();
            gbar();
        }
    }

    // ---------- solve mode 0 (block 0) ----------
    if (bid == 0) {
        int i = tid;
        float y[CC];
#pragma unroll
        for (int c = 0; c < CC; c++) y[c] = d_Qn[i * CC + c];
        for (int jb = 0; jb < HH; jb += 64) {
            for (int j = jb; j < jb + 64; j++) {
                if (i == j) {
                    float dgl = d_dinvf[j];
#pragma unroll
                    for (int c = 0; c < CC; c++) { y[c] *= dgl; shy[j - jb][c] = y[c]; }
                }
                __syncthreads();
                if (i > j && i < jb + 64) {
                    float lij = d_Gf[i * HH + j];
#pragma unroll
                    for (int c = 0; c < CC; c++) y[c] -= lij * shy[j - jb][c];
                }
                __syncthreads();
            }
            if (i >= jb + 64) {
                for (int t = 0; t < 64; t++) {
                    float lij = d_Gf[i * HH + jb + t];
#pragma unroll
                    for (int c = 0; c < CC; c++) y[c] -= lij * shy[t][c];
                }
            }
            __syncthreads();
        }
        for (int jb = HH - 64; jb >= 0; jb -= 64) {
            for (int j = jb + 63; j >= jb; j--) {
                if (i == j) {
                    float dgl = d_dinvf[j];
#pragma unroll
                    for (int c = 0; c < CC; c++) { y[c] *= dgl; shy[j - jb][c] = y[c]; }
                }
                __syncthreads();
                if (i >= jb && i < j) {
                    float lji = d_Gf[j * HH + i];
#pragma unroll
                    for (int c = 0; c < CC; c++) y[c] -= lji * shy[j - jb][c];
                }
                __syncthreads();
            }
            if (i < jb) {
                for (int t = 0; t < 64; t++) {
                    float lji = d_Gf[(jb + t) * HH + i];
#pragma unroll
                    for (int c = 0; c < CC; c++) y[c] -= lji * shy[t][c];
                }
            }
            __syncthreads();
        }
#pragma unroll
        for (int c = 0; c < CC; c++) d_wo[i * CC + c] = y[c];
    }
    gbar();

    // ---------- residual (all blocks, warp per row) ----------
    {
        for (int i = tid; i < HH * CC; i += 1024) u.sw[i] = d_wo[i];
        __syncthreads();
        int row = bid * 32 + wid;   // exactly 1024 rows
        float s[CC], comp[CC];
#pragma unroll
        for (int c = 0; c < CC; c++) {
            s[c] = (lane == 0) ? d_Qn[row * CC + c] : 0.f;
            comp[c] = 0.f;
        }
        const float* arow = &d_GA[row * HH];
        for (int j = lane; j < HH; j += 32) {
            float na = -arow[j];
#pragma unroll
            for (int c = 0; c < CC; c++) {
                float w = u.sw[j * CC + c];
                float p = na * w;
                float e = fmaf(na, w, -p);
                float t = s[c] + p;
                float bb = t - s[c];
                float err = (s[c] - (t - bb)) + (p - bb);
                s[c] = t;
                comp[c] += err + e;
            }
        }
#pragma unroll
        for (int c = 0; c < CC; c++) {
#pragma unroll
            for (int off2 = 16; off2 > 0; off2 >>= 1) {
                float s2 = __shfl_xor_sync(0xffffffffu, s[c], off2);
                float c2 = __shfl_xor_sync(0xffffffffu, comp[c], off2);
                float t = s[c] + s2;
                float bb = t - s[c];
                float err = (s[c] - (t - bb)) + (s2 - bb);
                s[c] = t;
                comp[c] += c2 + err;
            }
        }
        if (lane == 0) {
#pragma unroll
            for (int c = 0; c < CC; c++) d_res[row * CC + c] = s[c] + comp[c];
        }
    }
    gbar();

    // ---------- solve mode 1 (block 0): wo += L^-T L^-1 res ----------
    if (bid == 0) {
        int i = tid;
        float y[CC];
#pragma unroll
        for (int c = 0; c < CC; c++) y[c] = d_res[i * CC + c];
        for (int jb = 0; jb < HH; jb += 64) {
            for (int j = jb; j < jb + 64; j++) {
                if (i == j) {
                    float dgl = d_dinvf[j];
#pragma unroll
                    for (int c = 0; c < CC; c++) { y[c] *= dgl; shy[j - jb][c] = y[c]; }
                }
                __syncthreads();
                if (i > j && i < jb + 64) {
                    float lij = d_Gf[i * HH + j];
#pragma unroll
                    for (int c = 0; c < CC; c++) y[c] -= lij * shy[j - jb][c];
                }
                __syncthreads();
            }
            if (i >= jb + 64) {
                for (int t = 0; t < 64; t++) {
                    float lij = d_Gf[i * HH + jb + t];
#pragma unroll
                    for (int c = 0; c < CC; c++) y[c] -= lij * shy[t][c];
                }
            }
            __syncthreads();
        }
        for (int jb = HH - 64; jb >= 0; jb -= 64) {
            for (int j = jb + 63; j >= jb; j--) {
                if (i == j) {
                    float dgl = d_dinvf[j];
#pragma unroll
                    for (int c = 0; c < CC; c++) { y[c] *= dgl; shy[j - jb][c] = y[c]; }
                }
                __syncthreads();
                if (i >= jb && i < j) {
                    float lji = d_Gf[j * HH + i];
#pragma unroll
                    for (int c = 0; c < CC; c++) y[c] -= lji * shy[j - jb][c];
                }
                __syncthreads();
            }
            if (i < jb) {
                for (int t = 0; t < 64; t++) {
                    float lji = d_Gf[(jb + t) * HH + i];
#pragma unroll
                    for (int c = 0; c < CC; c++) y[c] -= lji * shy[t][c];
                }
            }
            __syncthreads();
        }
#pragma unroll
        for (int c = 0; c < CC; c++) d_wo[i * CC + c] += y[c];
    }
}

// ---------------- final ----------------
__global__ __launch_bounds__(256) void final_kernel(float* __restrict__ out) {
    __shared__ float sw[HH * CC];
    int tid = threadIdx.x;
    for (int i = tid; i < HH * CC; i += 256) sw[i] = d_wo[i];
    __syncthreads();
    int warp = tid >> 5, lane = tid & 31;
    int n = blockIdx.x * 8 + warp;
    if (n >= NN) return;
    const float* a = &d_featH[(long long)n * HH];
    float acc[CC];
#pragma unroll
    for (int c = 0; c < CC; c++) acc[c] = 0.f;
#pragma unroll
    for (int h = lane; h < HH; h += 32) {
        float v = a[h];
#pragma unroll
        for (int c = 0; c < CC; c++) acc[c] += v * sw[h * CC + c];
    }
#pragma unroll
    for (int c = 0; c < CC; c++) {
#pragma unroll
        for (int off = 16; off > 0; off >>= 1)
            acc[c] += __shfl_xor_sync(0xffffffffu, acc[c], off);
    }
    if (lane == 0) {
#pragma unroll
        for (int c = 0; c < CC; c++) out[(long long)n * CC + c] = acc[c];
    }
}

// ---------------- launcher ----------------
extern "C" void kernel_launch(void* const* d_in, const int* in_sizes, int n_in,
                              void* d_out, int out_size) {
    const float* feat   = (const float*)d_in[0];
    const float* proto  = (const float*)d_in[1];
    const float* wrand  = (const float*)d_in[2];
    const float* Qin    = (const float*)d_in[3];
    const float* Gin    = (const float*)d_in[4];
    const float* coords = (const float*)d_in[5];
    const float* normz  = (const float*)d_in[6];
    const void*  nidx   = (const void*)d_in[7];
    float* out = (float*)d_out;

    cudaFuncSetAttribute(gram_hmma_kernel,
                         cudaFuncAttributeMaxDynamicSharedMemorySize, GS_TOTAL);

    preds_kernel<<<(NN + 255) / 256, 256>>>(feat, proto);               // 0
    mask_kernel<<<NBLK, 256>>>(coords, normz, nidx);                    // 1
    scan_kernel<<<1, 512>>>();                                          // 2
    feath_kernel<<<dim3(HH / 64, (NN + 63) / 64), 256>>>(feat, wrand);  // 3 <- ncu slot
    scatter_kernel<<<NBLK, 256>>>();                                    // 4
    compact_kernel<<<dim3(HH / 64, 64), 256>>>();                       // 5
    gram_hmma_kernel<<<dim3(NTRI, GSPLIT), 1024, GS_TOTAL>>>();         // 6
    greduce_kernel<<<NTRI, 256>>>();                                    // 7
    qpart_kernel<<<dim3(HH / 256, NCHUNK), 256>>>();                    // 8
    qreduce_kernel<<<(HH * CC + 255) / 256, 256>>>(Qin);                // 9
    convm_kernel<<<(HH * HH) / 256, 256>>>(Gin);                        // 10
    chol_fused<<<NB, 1024>>>();                                         // 11
    final_kernel<<<(NN + 7) / 8, 256>>>(out);                           // 12
}

// round 16
// speedup vs baseline: 1.0436x; 1.0436x over previous
#include <cuda_runtime.h>
#include <cuda_bf16.h>
#include <math.h>
#include <stdint.h>

#define NN 100000
#define KK 20
#define DD 96
#define HH 1024
#define CC 7
#define KPAD 100096
#define GSPLIT 4
#define NTRI 36
#define NCHUNK 32
#define NBLK 391
#define NB 32                      // persistent-kernel block count
#define PB 128                     // cholesky panel size
#define CSM_FLOATS 16896           // max(128*132, 2*64*65, 7168)

// gram smem geometry
#define GS_ROWB 144
#define GS_TILE (128 * GS_ROWB)
#define GS_STAGE (4 * GS_TILE)
#define GS_TOTAL (2 * GS_STAGE)

// ---------------- scratch ----------------
static __device__ int           d_preds[NN];
static __device__ float         d_maskf[NN];
static __device__ int           d_bcnt[NBLK];
static __device__ int           d_boff[NBLK];
static __device__ int           d_nact;
static __device__ int           d_nchunk;
static __device__ int           d_active[NN];
static __device__ float         d_featH[(long long)NN * HH];
static __device__ __nv_bfloat16 d_Fhi[(long long)HH * KPAD];
static __device__ __nv_bfloat16 d_Flo[(long long)HH * KPAD];
static __device__ float         d_Spart[GSPLIT * NTRI * 128 * 128];
static __device__ float         d_Qpart[NCHUNK * HH * CC];
static __device__ float         d_Qn[HH * CC];
static __device__ float         d_Gn[HH * HH];
static __device__ float         d_GA[HH * HH];
static __device__ float         d_Gf[HH * HH];
static __device__ float         d_dinvf[HH];
static __device__ float         d_res[HH * CC];
static __device__ float         d_wo[HH * CC];
static __device__ unsigned int  g_cnt = 0;
static __device__ unsigned int  g_gen = 0;

// ---------------- ptx helpers ----------------
__device__ __forceinline__ uint32_t smem_to_u32(const void* smem_ptr) {
    uint32_t addr;
    asm("{ .reg .u64 tmp; cvta.to.shared.u64 tmp, %1; cvt.u32.u64 %0, tmp; }"
        : "=r"(addr) : "l"(smem_ptr));
    return addr;
}
#define CP_ASYNC16(dst, src) \
    asm volatile("cp.async.cg.shared.global [%0], [%1], 16;" :: "r"(dst), "l"(src))
#define CP_COMMIT() asm volatile("cp.async.commit_group;" ::: "memory")
#define CP_WAIT1()  asm volatile("cp.async.wait_group 1;" ::: "memory")
#define CP_WAIT0()  asm volatile("cp.async.wait_group 0;" ::: "memory")
#define LDSM4(r, addr) \
    asm volatile("ldmatrix.sync.aligned.m8n8.x4.shared.b16 {%0,%1,%2,%3}, [%4];" \
        : "=r"((r)[0]), "=r"((r)[1]), "=r"((r)[2]), "=r"((r)[3]) : "r"(addr))
#define MMA16816(c, a, b) \
    asm volatile("mma.sync.aligned.m16n8k16.row.col.f32.bf16.bf16.f32 " \
        "{%0,%1,%2,%3}, {%4,%5,%6,%7}, {%8,%9}, {%0,%1,%2,%3};" \
        : "+f"((c)[0]), "+f"((c)[1]), "+f"((c)[2]), "+f"((c)[3]) \
        : "r"((a)[0]), "r"((a)[1]), "r"((a)[2]), "r"((a)[3]), "r"((b)[0]), "r"((b)[1]))

__device__ __forceinline__ unsigned long long ffma2(unsigned long long a,
                                                    unsigned long long b,
                                                    unsigned long long c) {
    unsigned long long d;
    asm("fma.rn.f32x2 %0, %1, %2, %3;" : "=l"(d) : "l"(a), "l"(b), "l"(c));
    return d;
}
__device__ __forceinline__ unsigned long long dup2(float x) {
    unsigned long long d;
    asm("mov.b64 %0, {%1, %1};" : "=l"(d) : "f"(x));
    return d;
}
__device__ __forceinline__ float2 up2(unsigned long long v) {
    float2 r;
    asm("mov.b64 {%0, %1}, %2;" : "=f"(r.x), "=f"(r.y) : "l"(v));
    return r;
}
__device__ __forceinline__ unsigned long long d2u(double d) {
    return (unsigned long long)__double_as_longlong(d);
}

// ---------------- preds ----------------
__global__ __launch_bounds__(256) void preds_kernel(const float* __restrict__ feat,
                                                    const float* __restrict__ proto) {
    __shared__ float sp[CC][DD];
    int tid = threadIdx.x;
    if (tid < CC) {
        float s = 0.f;
        for (int k = 0; k < DD; k++) { float v = proto[tid * DD + k]; s += v * v; }
        float inv = 1.f / fmaxf(sqrtf(s), 1e-12f);
        for (int k = 0; k < DD; k++) sp[tid][k] = proto[tid * DD + k] * inv;
    }
    __syncthreads();
    int n = blockIdx.x * 256 + tid;
    if (n >= NN) return;
    const float* f = feat + (long long)n * DD;
    float acc[CC];
#pragma unroll
    for (int c = 0; c < CC; c++) acc[c] = 0.f;
#pragma unroll 4
    for (int k = 0; k < DD; k++) {
        float fk = f[k];
#pragma unroll
        for (int c = 0; c < CC; c++) acc[c] += fk * sp[c][k];
    }
    float best = acc[0];
    int bi = 0;
#pragma unroll
    for (int c = 1; c < CC; c++)
        if (acc[c] > best) { best = acc[c]; bi = c; }
    d_preds[n] = bi;
}

// ---------------- mask + per-block count ----------------
__global__ __launch_bounds__(256) void mask_kernel(const float* __restrict__ coords,
                                                   const float* __restrict__ normz,
                                                   const void* __restrict__ nidx) {
    __shared__ int wsum[8];
    int tid = threadIdx.x;
    int n = blockIdx.x * 256 + tid;
    bool mk = false;
    if (n < NN) {
        const int* pw = (const int*)nidx;
        int is64 = 1;
#pragma unroll
        for (int k = 1; k < 40; k += 2) is64 &= (pw[k] == 0);
        int p = d_preds[n];
        const long long* ni64 = (const long long*)nidx;
        const int*       ni32 = (const int*)nidx;
        int cnt = 0;
#pragma unroll
        for (int k = 0; k < KK; k++) {
            long long raw = is64 ? ni64[(long long)n * KK + k]
                                 : (long long)ni32[(long long)n * KK + k];
            unsigned int idx = (unsigned int)raw;
            if (idx >= NN) idx = 0;
            cnt += (d_preds[idx] == p);
        }
        bool cmask = cnt > 16;
        bool plane   = (p == 2) | (p == 3) | (p == 4);
        bool manmade = (p == 5);
        bool other   = (p == 0) | (p == 1) | (p == 6);
        float nz = normz[n];
        float z  = coords[(long long)n * 3 + 2];
        bool ground = plane && (nz > 0.9f) && (z < -10.0f);
        bool g = ground || other || manmade;
        bool m = (manmade && (nz < 0.1f)) || other || plane;
        mk = cmask && g && m;
        d_maskf[n] = mk ? 1.f : 0.f;
    }
    unsigned int b = __ballot_sync(0xffffffffu, mk);
    if ((tid & 31) == 0) wsum[tid >> 5] = __popc(b);
    __syncthreads();
    if (tid == 0) {
        int s = 0;
#pragma unroll
        for (int w = 0; w < 8; w++) s += wsum[w];
        d_bcnt[blockIdx.x] = s;
    }
}

// ---------------- scan ----------------
__global__ __launch_bounds__(512) void scan_kernel() {
    __shared__ int s[NBLK];
    int tid = threadIdx.x;
    if (tid < NBLK) s[tid] = d_bcnt[tid];
    __syncthreads();
    if (tid == 0) {
        int run = 0;
        for (int i = 0; i < NBLK; i++) { int v = s[i]; s[i] = run; run += v; }
        d_nact = run;
        d_nchunk = (run + 63) / 64;
    }
    __syncthreads();
    if (tid < NBLK) d_boff[tid] = s[tid];
}

// ---------------- scatter ----------------
__global__ __launch_bounds__(256) void scatter_kernel() {
    __shared__ int wcnt[8];
    __shared__ int woff[8];
    int tid = threadIdx.x;
    int n = blockIdx.x * 256 + tid;
    bool mk = (n < NN) && (d_maskf[n] != 0.f);
    unsigned int b = __ballot_sync(0xffffffffu, mk);
    int lane = tid & 31, wid = tid >> 5;
    if (lane == 0) wcnt[wid] = __popc(b);
    __syncthreads();
    if (tid == 0) {
        int run = 0;
#pragma unroll
        for (int w = 0; w < 8; w++) { woff[w] = run; run += wcnt[w]; }
    }
    __syncthreads();
    if (mk) {
        int rank = __popc(b & ((1u << lane) - 1u));
        d_active[d_boff[blockIdx.x] + woff[wid] + rank] = n;
    }
}

// ---------------- feath: 128x128 tile, 8x8/thread, fp32 only ----------------
#define FB_STRIDE 132
__global__ __launch_bounds__(256) void feath_kernel(const float* __restrict__ feat,
                                                    const float* __restrict__ w) {
    __shared__ __align__(16) float As[32][FB_STRIDE];
    __shared__ __align__(16) float Bs[32][FB_STRIDE];
    int tid = threadIdx.x;
    int h0 = blockIdx.x * 128;
    int n0 = blockIdx.y * 128;
    int tx = tid & 15, ty = tid >> 4;

    unsigned long long acc[8][4];
#pragma unroll
    for (int r = 0; r < 8; r++)
#pragma unroll
        for (int c = 0; c < 4; c++) acc[r][c] = 0ull;

    for (int k0 = 0; k0 < DD; k0 += 32) {
        for (int i = tid; i < 4096; i += 256) {          // As[k][n-local]
            int k = i & 31, m = i >> 5;
            int n = n0 + m;
            As[k][m] = (n < NN) ? feat[(long long)n * DD + k0 + k] : 0.f;
        }
        for (int i = tid; i < 4096; i += 256) {          // Bs[k][h-local]
            int k = i >> 7, m = i & 127;
            Bs[k][m] = w[(k0 + k) * HH + h0 + m];
        }
        __syncthreads();
#pragma unroll
        for (int k = 0; k < 32; k++) {
            float4 a0 = *reinterpret_cast<const float4*>(&As[k][ty * 8]);
            float4 a1 = *reinterpret_cast<const float4*>(&As[k][ty * 8 + 4]);
            double2 b0 = *reinterpret_cast<const double2*>(&Bs[k][tx * 8]);
            double2 b1 = *reinterpret_cast<const double2*>(&Bs[k][tx * 8 + 4]);
            unsigned long long bp0 = d2u(b0.x), bp1 = d2u(b0.y);
            unsigned long long bp2 = d2u(b1.x), bp3 = d2u(b1.y);
            float av[8] = {a0.x, a0.y, a0.z, a0.w, a1.x, a1.y, a1.z, a1.w};
#pragma unroll
            for (int rn = 0; rn < 8; rn++) {
                unsigned long long ap = dup2(av[rn]);
                acc[rn][0] = ffma2(ap, bp0, acc[rn][0]);
                acc[rn][1] = ffma2(ap, bp1, acc[rn][1]);
                acc[rn][2] = ffma2(ap, bp2, acc[rn][2]);
                acc[rn][3] = ffma2(ap, bp3, acc[rn][3]);
            }
        }
        __syncthreads();
    }
#pragma unroll
    for (int rn = 0; rn < 8; rn++) {
        int n = n0 + ty * 8 + rn;
        if (n < NN) {
            float2 f0 = up2(acc[rn][0]);
            float2 f1 = up2(acc[rn][1]);
            float2 f2 = up2(acc[rn][2]);
            float2 f3 = up2(acc[rn][3]);
            float* dst = &d_featH[(long long)n * HH + h0 + tx * 8];
            *reinterpret_cast<float4*>(dst) =
                make_float4(fmaxf(f0.x, 0.f), fmaxf(f0.y, 0.f),
                            fmaxf(f1.x, 0.f), fmaxf(f1.y, 0.f));
            *reinterpret_cast<float4*>(dst + 4) =
                make_float4(fmaxf(f2.x, 0.f), fmaxf(f2.y, 0.f),
                            fmaxf(f3.x, 0.f), fmaxf(f3.y, 0.f));
        }
    }
}

// ---------------- compact ----------------
__global__ __launch_bounds__(256) void compact_kernel() {
    __shared__ float sT[64][65];
    int tid = threadIdx.x;
    int h0 = blockIdx.x * 64;
    int NCH = d_nchunk;
    int nact = d_nact;
    for (int cb = blockIdx.y; cb < NCH; cb += 64) {
        int p0 = cb * 64;
        int pl = tid >> 2, seg = tid & 3;
        int p = p0 + pl;
        int n = (p < nact) ? d_active[p] : -1;
        float4 v0, v1, v2, v3;
        if (n >= 0) {
            const float* src = &d_featH[(long long)n * HH + h0 + seg * 16];
            v0 = *reinterpret_cast<const float4*>(src);
            v1 = *reinterpret_cast<const float4*>(src + 4);
            v2 = *reinterpret_cast<const float4*>(src + 8);
            v3 = *reinterpret_cast<const float4*>(src + 12);
        } else {
            v0 = v1 = v2 = v3 = make_float4(0.f, 0.f, 0.f, 0.f);
        }
        __syncthreads();
        {
            int hb = seg * 16;
            sT[hb + 0][pl] = v0.x;  sT[hb + 1][pl] = v0.y;
            sT[hb + 2][pl] = v0.z;  sT[hb + 3][pl] = v0.w;
            sT[hb + 4][pl] = v1.x;  sT[hb + 5][pl] = v1.y;
            sT[hb + 6][pl] = v1.z;  sT[hb + 7][pl] = v1.w;
            sT[hb + 8][pl] = v2.x;  sT[hb + 9][pl] = v2.y;
            sT[hb + 10][pl] = v2.z; sT[hb + 11][pl] = v2.w;
            sT[hb + 12][pl] = v3.x; sT[hb + 13][pl] = v3.y;
            sT[hb + 14][pl] = v3.z; sT[hb + 15][pl] = v3.w;
        }
        __syncthreads();
        {
            int hrow = tid >> 2, q = tid & 3;
            __align__(16) __nv_bfloat16 hb16[16], lb16[16];
#pragma unroll
            for (int i = 0; i < 16; i++) {
                float v = sT[hrow][q * 16 + i];
                __nv_bfloat16 h = __float2bfloat16(v);
                hb16[i] = h;
                lb16[i] = __float2bfloat16(v - __bfloat162float(h));
            }
            size_t gb = (size_t)(h0 + hrow) * KPAD + p0 + q * 16;
            *reinterpret_cast<uint4*>(&d_Fhi[gb])     = *reinterpret_cast<uint4*>(&hb16[0]);
            *reinterpret_cast<uint4*>(&d_Fhi[gb + 8]) = *reinterpret_cast<uint4*>(&hb16[8]);
            *reinterpret_cast<uint4*>(&d_Flo[gb])     = *reinterpret_cast<uint4*>(&lb16[0]);
            *reinterpret_cast<uint4*>(&d_Flo[gb + 8]) = *reinterpret_cast<uint4*>(&lb16[8]);
        }
    }
}

// ---------------- Gram (dynamic chunk count) ----------------
__global__ __launch_bounds__(1024, 1) void gram_hmma_kernel() {
    extern __shared__ __align__(16) char smg[];
    uint32_t sb = smem_to_u32(smg);
    int tid = threadIdx.x;
    int t = blockIdx.x, sp = blockIdx.y;
    int bi = 0;
    while ((bi + 1) * (bi + 2) / 2 <= t) bi++;
    int bj = t - bi * (bi + 1) / 2;
    int h10 = bi * 128, h20 = bj * 128;

    int NCH = d_nchunk;
    int cps = (NCH + GSPLIT - 1) / GSPLIT;
    int c0 = sp * cps;
    int cnt = min(c0 + cps, NCH) - c0;
    float* out = &d_Spart[(size_t)(sp * NTRI + t) * 128 * 128];

    if (cnt <= 0) {
        float4 z = make_float4(0.f, 0.f, 0.f, 0.f);
        for (int i = tid; i < 128 * 128 / 4; i += 1024)
            *reinterpret_cast<float4*>(&out[i * 4]) = z;
        return;
    }

    int lrow = tid >> 3, lseg = tid & 7;
    size_t kstart = (size_t)c0 * 64 + lseg * 8;
    const __nv_bfloat16* pAh = d_Fhi + (size_t)(h10 + lrow) * KPAD + kstart;
    const __nv_bfloat16* pAl = d_Flo + (size_t)(h10 + lrow) * KPAD + kstart;
    const __nv_bfloat16* pBh = d_Fhi + (size_t)(h20 + lrow) * KPAD + kstart;
    const __nv_bfloat16* pBl = d_Flo + (size_t)(h20 + lrow) * KPAD + kstart;
    uint32_t ldst = sb + lrow * GS_ROWB + lseg * 16;

    int wid = tid >> 5, lane = tid & 31;
    int mbase = (wid >> 2) * 16, nbase = (wid & 3) * 32;
    int arow = (lane & 7) + ((lane >> 3) & 1) * 8;
    int acol = ((lane >> 4) & 1) * 8;
    int brow = (lane & 7) + ((lane >> 4) & 1) * 8;
    int bcol = ((lane >> 3) & 1) * 8;
    uint32_t aoff = (uint32_t)(((mbase + arow) * 72 + acol) * 2);
    uint32_t boff[2];
#pragma unroll
    for (int nj = 0; nj < 2; nj++)
        boff[nj] = (uint32_t)(((nbase + nj * 16 + brow) * 72 + bcol) * 2);

    float acc[4][4];
#pragma unroll
    for (int b = 0; b < 4; b++)
#pragma unroll
        for (int c = 0; c < 4; c++) acc[b][c] = 0.f;

    CP_ASYNC16(ldst + 0 * GS_TILE, pAh);
    CP_ASYNC16(ldst + 1 * GS_TILE, pAl);
    CP_ASYNC16(ldst + 2 * GS_TILE, pBh);
    CP_ASYNC16(ldst + 3 * GS_TILE, pBl);
    CP_COMMIT();

    for (int c = 0; c < cnt; c++) {
        if (c + 1 < cnt) {
            uint32_t base = ldst + ((c + 1) & 1) * GS_STAGE;
            size_t ko = (size_t)(c + 1) * 64;
            CP_ASYNC16(base + 0 * GS_TILE, pAh + ko);
            CP_ASYNC16(base + 1 * GS_TILE, pAl + ko);
            CP_ASYNC16(base + 2 * GS_TILE, pBh + ko);
            CP_ASYNC16(base + 3 * GS_TILE, pBl + ko);
            CP_COMMIT();
            CP_WAIT1();
        } else {
            CP_WAIT0();
        }
        __syncthreads();
        uint32_t stg = sb + (c & 1) * GS_STAGE;
#pragma unroll
        for (int ks = 0; ks < 4; ks++) {
            uint32_t kb = ks * 32;
            uint32_t ah[4], al[4], bh[4][2], bl[4][2];
            LDSM4(ah, stg + 0 * GS_TILE + aoff + kb);
#pragma unroll
            for (int nj = 0; nj < 2; nj++) {
                uint32_t r[4];
                LDSM4(r, stg + 2 * GS_TILE + boff[nj] + kb);
                bh[nj * 2][0] = r[0]; bh[nj * 2][1] = r[1];
                bh[nj * 2 + 1][0] = r[2]; bh[nj * 2 + 1][1] = r[3];
            }
#pragma unroll
            for (int nj = 0; nj < 4; nj++) MMA16816(acc[nj], ah, bh[nj]);
#pragma unroll
            for (int nj = 0; nj < 2; nj++) {
                uint32_t r[4];
                LDSM4(r, stg + 3 * GS_TILE + boff[nj] + kb);
                bl[nj * 2][0] = r[0]; bl[nj * 2][1] = r[1];
                bl[nj * 2 + 1][0] = r[2]; bl[nj * 2 + 1][1] = r[3];
            }
#pragma unroll
            for (int nj = 0; nj < 4; nj++) MMA16816(acc[nj], ah, bl[nj]);
            LDSM4(al, stg + 1 * GS_TILE + aoff + kb);
#pragma unroll
            for (int nj = 0; nj < 4; nj++) MMA16816(acc[nj], al, bh[nj]);
        }
        __syncthreads();
    }

    int g = lane >> 2, q = lane & 3;
#pragma unroll
    for (int nj = 0; nj < 4; nj++) {
        int r0 = mbase + g;
        int cc = nbase + nj * 8 + q * 2;
        *reinterpret_cast<float2*>(&out[r0 * 128 + cc]) =
            make_float2(acc[nj][0], acc[nj][1]);
        *reinterpret_cast<float2*>(&out[(r0 + 8) * 128 + cc]) =
            make_float2(acc[nj][2], acc[nj][3]);
    }
}

// ---------------- reduce split-K partials ----------------
__global__ __launch_bounds__(256) void greduce_kernel() {
    int t = blockIdx.x;
    int bi = 0;
    while ((bi + 1) * (bi + 2) / 2 <= t) bi++;
    int bj = t - bi * (bi + 1) / 2;
    for (int i = threadIdx.x; i < 128 * 128 / 4; i += 256) {
        float4 s = make_float4(0.f, 0.f, 0.f, 0.f);
#pragma unroll
        for (int sp = 0; sp < GSPLIT; sp++) {
            float4 v = *reinterpret_cast<const float4*>(
                &d_Spart[(size_t)(sp * NTRI + t) * 128 * 128 + i * 4]);
            s.x += v.x; s.y += v.y; s.z += v.z; s.w += v.w;
        }
        int r = (i * 4) >> 7, c = (i * 4) & 127;
        *reinterpret_cast<float4*>(&d_Gn[(bi * 128 + r) * HH + bj * 128 + c]) = s;
    }
}

// ---------------- Qn partials over active list ----------------
__global__ __launch_bounds__(256) void qpart_kernel() {
    int h = blockIdx.x * 256 + threadIdx.x;
    int chunk = blockIdx.y;
    int nact = d_nact;
    int stride = (nact + NCHUNK - 1) / NCHUNK;
    int p0 = chunk * stride;
    int p1 = min(p0 + stride, nact);
    float a0 = 0, a1 = 0, a2 = 0, a3 = 0, a4 = 0, a5 = 0, a6 = 0;
    for (int p = p0; p < p1; p++) {
        int n = d_active[p];
        float v = d_featH[(long long)n * HH + h];
        int pr = d_preds[n];
        a0 += (pr == 0) ? v : 0.f;
        a1 += (pr == 1) ? v : 0.f;
        a2 += (pr == 2) ? v : 0.f;
        a3 += (pr == 3) ? v : 0.f;
        a4 += (pr == 4) ? v : 0.f;
        a5 += (pr == 5) ? v : 0.f;
        a6 += (pr == 6) ? v : 0.f;
    }
    int o = (chunk * HH + h) * CC;
    d_Qpart[o + 0] = a0; d_Qpart[o + 1] = a1; d_Qpart[o + 2] = a2; d_Qpart[o + 3] = a3;
    d_Qpart[o + 4] = a4; d_Qpart[o + 5] = a5; d_Qpart[o + 6] = a6;
}

__global__ void qreduce_kernel(const float* __restrict__ Qin) {
    int idx = blockIdx.x * 256 + threadIdx.x;
    if (idx >= HH * CC) return;
    float s = Qin[idx];
    for (int ch = 0; ch < NCHUNK; ch++) s += d_Qpart[ch * HH * CC + idx];
    d_Qn[idx] = s;
}

// ---------------- mirror + Gin + ridge ----------------
__global__ void convm_kernel(const float* __restrict__ Gin) {
    int idx = blockIdx.x * 256 + threadIdx.x;
    int i = idx >> 10, j = idx & 1023;
    float v = (i >= j) ? d_Gn[i * HH + j] : d_Gn[j * HH + i];
    float a = v + Gin[idx] + ((i == j) ? 100.0f : 0.0f);
    d_GA[idx] = a;
    d_Gf[idx] = a;
}

// ================= fused Cholesky (128-panel) + solves =================
__device__ __forceinline__ void gbar() {
    __threadfence();
    __syncthreads();
    if (threadIdx.x == 0) {
        unsigned int gen = atomicAdd(&g_gen, 0u);
        if (atomicAdd(&g_cnt, 1u) == NB - 1) {
            atomicExch(&g_cnt, 0u);
            __threadfence();
            atomicAdd(&g_gen, 1u);
        } else {
            while (atomicAdd(&g_gen, 0u) == gen) { __nanosleep(64); }
        }
        __threadfence();
    }
    __syncthreads();
}

__global__ __launch_bounds__(1024, 1) void chol_fused() {
    extern __shared__ float csm[];       // CSM_FLOATS
    __shared__ float shy[64][CC];
    __shared__ float di_s[PB];

    int tid = threadIdx.x;
    int bid = blockIdx.x;
    int lane = tid & 31, wid = tid >> 5;

    // ---------- factorization: 8 rounds of 128-panel ----------
    for (int kb = 0; kb < HH / PB; kb++) {
        int off = kb * PB;
        // phase A: potf2 128x128 in smem by block 0 (8 threads/row)
        if (bid == 0) {
            float* S = csm;              // [128][132]
            for (int i = tid; i < PB * PB; i += 1024)
                S[(i >> 7) * 132 + (i & 127)] = d_Gf[(off + (i >> 7)) * HH + off + (i & 127)];
            __syncthreads();
            int row = tid & 127, s8 = tid >> 7;   // s8: 0..7
            for (int j = 0; j < PB; j++) {
                if (row == j && s8 == 0) {
                    float dv = sqrtf(fmaxf(S[j * 132 + j], 1e-20f));
                    S[j * 132 + j] = dv;
                    di_s[j] = 1.0f / dv;
                }
                __syncthreads();
                if (row > j && s8 == 0) S[row * 132 + j] *= di_s[j];
                __syncthreads();
                if (row > j) {
                    float lij = S[row * 132 + j];
                    for (int k = j + 1 + s8; k <= row; k += 8)
                        S[row * 132 + k] -= lij * S[k * 132 + j];
                }
                __syncthreads();
            }
            for (int i = tid; i < PB * PB; i += 1024) {
                int r = i >> 7, c = i & 127;
                if (r >= c) d_Gf[(off + r) * HH + off + c] = S[r * 132 + c];
            }
            if (tid < PB) d_dinvf[off + tid] = di_s[tid];
            __syncthreads();
        }
        gbar();

        int base = off + PB;
        int rows = HH - base;
        if (rows > 0) {
            // phase B: trsm, warp-per-row, lane owns cols 4l..4l+3
            float* L = csm;              // [128][132]
            for (int i = tid; i < PB * PB; i += 1024)
                L[(i >> 7) * 132 + (i & 127)] = d_Gf[(off + (i >> 7)) * HH + off + (i & 127)];
            if (tid < PB) di_s[tid] = d_dinvf[off + tid];
            __syncthreads();
            int gw = bid * 32 + wid;     // 0..1023
            if (gw < rows) {
                int r = base + gw;
                float* a = &d_Gf[r * HH + off];
                int c0 = lane * 4;
                float x0 = a[c0], x1 = a[c0 + 1], x2 = a[c0 + 2], x3 = a[c0 + 3];
#pragma unroll
                for (int j = 0; j < PB; j++) {
                    int owner = j >> 2;
                    int qj = j & 3;
                    float xown = (qj == 0) ? x0 : (qj == 1) ? x1 : (qj == 2) ? x2 : x3;
                    float xj = __shfl_sync(0xffffffffu, xown * di_s[j], owner);
                    if (lane == owner) {
                        if (qj == 0) x0 = xj; else if (qj == 1) x1 = xj;
                        else if (qj == 2) x2 = xj; else x3 = xj;
                    }
                    if (c0 + 0 > j) x0 -= xj * L[(c0 + 0) * 132 + j];
                    if (c0 + 1 > j) x1 -= xj * L[(c0 + 1) * 132 + j];
                    if (c0 + 2 > j) x2 -= xj * L[(c0 + 2) * 132 + j];
                    if (c0 + 3 > j) x3 -= xj * L[(c0 + 3) * 132 + j];
                }
                a[c0] = x0; a[c0 + 1] = x1; a[c0 + 2] = x2; a[c0 + 3] = x3;
            }
            gbar();

            // phase C: syrk K=128 (two K=64 passes), 64x64 lower tiles
            float* Li = csm;             // [64][65]
            float* Lj = csm + 64 * 65;   // [64][65]
            int T = rows / 64;
            int ntiles = T * (T + 1) / 2;
            for (int idx = bid; idx < ntiles; idx += NB) {
                int ti = 0;
                while ((ti + 1) * (ti + 2) / 2 <= idx) ti++;
                int tj = idx - ti * (ti + 1) / 2;
                int i0 = base + ti * 64, j0 = base + tj * 64;
                int tx = tid & 63, tg = tid >> 6;
                float acc[4] = {0.f, 0.f, 0.f, 0.f};
#pragma unroll
                for (int koff = 0; koff < PB; koff += 64) {
                    __syncthreads();
                    for (int i = tid; i < 64 * 64; i += 1024) {
                        Li[(i >> 6) * 65 + (i & 63)] =
                            d_Gf[(i0 + (i >> 6)) * HH + off + koff + (i & 63)];
                        Lj[(i >> 6) * 65 + (i & 63)] =
                            d_Gf[(j0 + (i >> 6)) * HH + off + koff + (i & 63)];
                    }
                    __syncthreads();
                    for (int t = 0; t < 64; t++) {
                        float bj = Lj[tx * 65 + t];
#pragma unroll
                        for (int s = 0; s < 4; s++) acc[s] += Li[(tg + s * 16) * 65 + t] * bj;
                    }
                }
#pragma unroll
                for (int s = 0; s < 4; s++)
                    d_Gf[(i0 + tg + s * 16) * HH + j0 + tx] -= acc[s];
            }
            gbar();
        } else {
            gbar();
            gbar();
        }
    }

    // ---------- solve mode 0 (block 0) ----------
    if (bid == 0) {
        int i = tid;
        float y[CC];
#pragma unroll
        for (int c = 0; c < CC; c++) y[c] = d_Qn[i * CC + c];
        for (int jb = 0; jb < HH; jb += 64) {
            for (int j = jb; j < jb + 64; j++) {
                if (i == j) {
                    float dgl = d_dinvf[j];
#pragma unroll
                    for (int c = 0; c < CC; c++) { y[c] *= dgl; shy[j - jb][c] = y[c]; }
                }
                __syncthreads();
                if (i > j && i < jb + 64) {
                    float lij = d_Gf[i * HH + j];
#pragma unroll
                    for (int c = 0; c < CC; c++) y[c] -= lij * shy[j - jb][c];
                }
                __syncthreads();
            }
            if (i >= jb + 64) {
                for (int t = 0; t < 64; t++) {
                    float lij = d_Gf[i * HH + jb + t];
#pragma unroll
                    for (int c = 0; c < CC; c++) y[c] -= lij * shy[t][c];
                }
            }
            __syncthreads();
        }
        for (int jb = HH - 64; jb >= 0; jb -= 64) {
            for (int j = jb + 63; j >= jb; j--) {
                if (i == j) {
                    float dgl = d_dinvf[j];
#pragma unroll
                    for (int c = 0; c < CC; c++) { y[c] *= dgl; shy[j - jb][c] = y[c]; }
                }
                __syncthreads();
                if (i >= jb && i < j) {
                    float lji = d_Gf[j * HH + i];
#pragma unroll
                    for (int c = 0; c < CC; c++) y[c] -= lji * shy[j - jb][c];
                }
                __syncthreads();
            }
            if (i < jb) {
                for (int t = 0; t < 64; t++) {
                    float lji = d_Gf[(jb + t) * HH + i];
#pragma unroll
                    for (int c = 0; c < CC; c++) y[c] -= lji * shy[t][c];
                }
            }
            __syncthreads();
        }
#pragma unroll
        for (int c = 0; c < CC; c++) d_wo[i * CC + c] = y[c];
    }
    gbar();

    // ---------- residual (all blocks, warp per row) ----------
    {
        float* sw = csm;                 // HH*CC floats
        for (int i = tid; i < HH * CC; i += 1024) sw[i] = d_wo[i];
        __syncthreads();
        int row = bid * 32 + wid;
        float s[CC], comp[CC];
#pragma unroll
        for (int c = 0; c < CC; c++) {
            s[c] = (lane == 0) ? d_Qn[row * CC + c] : 0.f;
            comp[c] = 0.f;
        }
        const float* arow = &d_GA[row * HH];
        for (int j = lane; j < HH; j += 32) {
            float na = -arow[j];
#pragma unroll
            for (int c = 0; c < CC; c++) {
                float w = sw[j * CC + c];
                float p = na * w;
                float e = fmaf(na, w, -p);
                float t = s[c] + p;
                float bb = t - s[c];
                float err = (s[c] - (t - bb)) + (p - bb);
                s[c] = t;
                comp[c] += err + e;
            }
        }
#pragma unroll
        for (int c = 0; c < CC; c++) {
#pragma unroll
            for (int off2 = 16; off2 > 0; off2 >>= 1) {
                float s2 = __shfl_xor_sync(0xffffffffu, s[c], off2);
                float c2 = __shfl_xor_sync(0xffffffffu, comp[c], off2);
                float t = s[c] + s2;
                float bb = t - s[c];
                float err = (s[c] - (t - bb)) + (s2 - bb);
                s[c] = t;
                comp[c] += c2 + err;
            }
        }
        if (lane == 0) {
#pragma unroll
            for (int c = 0; c < CC; c++) d_res[row * CC + c] = s[c] + comp[c];
        }
    }
    gbar();

    // ---------- solve mode 1 (block 0): wo += L^-T L^-1 res ----------
    if (bid == 0) {
        int i = tid;
        float y[CC];
#pragma unroll
        for (int c = 0; c < CC; c++) y[c] = d_res[i * CC + c];
        for (int jb = 0; jb < HH; jb += 64) {
            for (int j = jb; j < jb + 64; j++) {
                if (i == j) {
                    float dgl = d_dinvf[j];
#pragma unroll
                    for (int c = 0; c < CC; c++) { y[c] *= dgl; shy[j - jb][c] = y[c]; }
                }
                __syncthreads();
                if (i > j && i < jb + 64) {
                    float lij = d_Gf[i * HH + j];
#pragma unroll
                    for (int c = 0; c < CC; c++) y[c] -= lij * shy[j - jb][c];
                }
                __syncthreads();
            }
            if (i >= jb + 64) {
                for (int t = 0; t < 64; t++) {
                    float lij = d_Gf[i * HH + jb + t];
#pragma unroll
                    for (int c = 0; c < CC; c++) y[c] -= lij * shy[t][c];
                }
            }
            __syncthreads();
        }
        for (int jb = HH - 64; jb >= 0; jb -= 64) {
            for (int j = jb + 63; j >= jb; j--) {
                if (i == j) {
                    float dgl = d_dinvf[j];
#pragma unroll
                    for (int c = 0; c < CC; c++) { y[c] *= dgl; shy[j - jb][c] = y[c]; }
                }
                __syncthreads();
                if (i >= jb && i < j) {
                    float lji = d_Gf[j * HH + i];
#pragma unroll
                    for (int c = 0; c < CC; c++) y[c] -= lji * shy[j - jb][c];
                }
                __syncthreads();
            }
            if (i < jb) {
                for (int t = 0; t < 64; t++) {
                    float lji = d_Gf[(jb + t) * HH + i];
#pragma unroll
                    for (int c = 0; c < CC; c++) y[c] -= lji * shy[t][c];
                }
            }
            __syncthreads();
        }
#pragma unroll
        for (int c = 0; c < CC; c++) d_wo[i * CC + c] += y[c];
    }
}

// ---------------- final ----------------
__global__ __launch_bounds__(256) void final_kernel(float* __restrict__ out) {
    __shared__ float sw[HH * CC];
    int tid = threadIdx.x;
    for (int i = tid; i < HH * CC; i += 256) sw[i] = d_wo[i];
    __syncthreads();
    int warp = tid >> 5, lane = tid & 31;
    int n = blockIdx.x * 8 + warp;
    if (n >= NN) return;
    const float* a = &d_featH[(long long)n * HH];
    float acc[CC];
#pragma unroll
    for (int c = 0; c < CC; c++) acc[c] = 0.f;
#pragma unroll
    for (int h = lane; h < HH; h += 32) {
        float v = a[h];
#pragma unroll
        for (int c = 0; c < CC; c++) acc[c] += v * sw[h * CC + c];
    }
#pragma unroll
    for (int c = 0; c < CC; c++) {
#pragma unroll
        for (int off = 16; off > 0; off >>= 1)
            acc[c] += __shfl_xor_sync(0xffffffffu, acc[c], off);
    }
    if (lane == 0) {
#pragma unroll
        for (int c = 0; c < CC; c++) out[(long long)n * CC + c] = acc[c];
    }
}

// ---------------- launcher ----------------
extern "C" void kernel_launch(void* const* d_in, const int* in_sizes, int n_in,
                              void* d_out, int out_size) {
    const float* feat   = (const float*)d_in[0];
    const float* proto  = (const float*)d_in[1];
    const float* wrand  = (const float*)d_in[2];
    const float* Qin    = (const float*)d_in[3];
    const float* Gin    = (const float*)d_in[4];
    const float* coords = (const float*)d_in[5];
    const float* normz  = (const float*)d_in[6];
    const void*  nidx   = (const void*)d_in[7];
    float* out = (float*)d_out;

    cudaFuncSetAttribute(gram_hmma_kernel,
                         cudaFuncAttributeMaxDynamicSharedMemorySize, GS_TOTAL);
    cudaFuncSetAttribute(chol_fused,
                         cudaFuncAttributeMaxDynamicSharedMemorySize, CSM_FLOATS * 4);

    preds_kernel<<<(NN + 255) / 256, 256>>>(feat, proto);                  // 0
    mask_kernel<<<NBLK, 256>>>(coords, normz, nidx);                       // 1
    scan_kernel<<<1, 512>>>();                                             // 2
    feath_kernel<<<dim3(HH / 128, (NN + 127) / 128), 256>>>(feat, wrand);  // 3 <- ncu slot
    scatter_kernel<<<NBLK, 256>>>();                                       // 4
    compact_kernel<<<dim3(HH / 64, 64), 256>>>();                          // 5
    gram_hmma_kernel<<<dim3(NTRI, GSPLIT), 1024, GS_TOTAL>>>();            // 6
    greduce_kernel<<<NTRI, 256>>>();                                       // 7
    qpart_kernel<<<dim3(HH / 256, NCHUNK), 256>>>();                       // 8
    qreduce_kernel<<<(HH * CC + 255) / 256, 256>>>(Qin);                   // 9
    convm_kernel<<<(HH * HH) / 256, 256>>>(Gin);                           // 10
    chol_fused<<<NB, 1024, CSM_FLOATS * 4>>>();                            // 11
    final_kernel<<<(NN + 7) / 8, 256>>>(out);                              // 12
}

// round 17
// speedup vs baseline: 1.0596x; 1.0153x over previous
#include <cuda_runtime.h>
#include <cuda_bf16.h>
#include <math.h>
#include <stdint.h>

#define NN 100000
#define KK 20
#define DD 96
#define HH 1024
#define CC 7
#define KPAD 100096
#define GSPLIT 4
#define NTRI 36
#define NCHUNK 32
#define NBLK 391
#define NB 32                      // persistent-kernel block count
#define PB 128                     // cholesky panel size
#define CSM_FLOATS 16896           // 128*132; >= 7168+4160 solve needs

// gram smem geometry
#define GS_ROWB 144
#define GS_TILE (128 * GS_ROWB)
#define GS_STAGE (4 * GS_TILE)
#define GS_TOTAL (2 * GS_STAGE)

// ---------------- scratch ----------------
static __device__ int           d_preds[NN];
static __device__ float         d_maskf[NN];
static __device__ int           d_bcnt[NBLK];
static __device__ int           d_boff[NBLK];
static __device__ int           d_nact;
static __device__ int           d_nchunk;
static __device__ int           d_active[NN];
static __device__ float         d_featH[(long long)NN * HH];
static __device__ __nv_bfloat16 d_Fhi[(long long)HH * KPAD];
static __device__ __nv_bfloat16 d_Flo[(long long)HH * KPAD];
static __device__ float         d_Spart[GSPLIT * NTRI * 128 * 128];
static __device__ float         d_Qpart[NCHUNK * HH * CC];
static __device__ float         d_Qn[HH * CC];
static __device__ float         d_Gn[HH * HH];
static __device__ float         d_GA[HH * HH];
static __device__ float         d_Gf[HH * HH];
static __device__ float         d_dinvf[HH];
static __device__ float         d_res[HH * CC];
static __device__ float         d_wo[HH * CC];
static __device__ unsigned int  g_cnt = 0;
static __device__ unsigned int  g_gen = 0;

// ---------------- ptx helpers ----------------
__device__ __forceinline__ uint32_t smem_to_u32(const void* smem_ptr) {
    uint32_t addr;
    asm("{ .reg .u64 tmp; cvta.to.shared.u64 tmp, %1; cvt.u32.u64 %0, tmp; }"
        : "=r"(addr) : "l"(smem_ptr));
    return addr;
}
#define CP_ASYNC16(dst, src) \
    asm volatile("cp.async.cg.shared.global [%0], [%1], 16;" :: "r"(dst), "l"(src))
#define CP_COMMIT() asm volatile("cp.async.commit_group;" ::: "memory")
#define CP_WAIT1()  asm volatile("cp.async.wait_group 1;" ::: "memory")
#define CP_WAIT0()  asm volatile("cp.async.wait_group 0;" ::: "memory")
#define LDSM4(r, addr) \
    asm volatile("ldmatrix.sync.aligned.m8n8.x4.shared.b16 {%0,%1,%2,%3}, [%4];" \
        : "=r"((r)[0]), "=r"((r)[1]), "=r"((r)[2]), "=r"((r)[3]) : "r"(addr))
#define MMA16816(c, a, b) \
    asm volatile("mma.sync.aligned.m16n8k16.row.col.f32.bf16.bf16.f32 " \
        "{%0,%1,%2,%3}, {%4,%5,%6,%7}, {%8,%9}, {%0,%1,%2,%3};" \
        : "+f"((c)[0]), "+f"((c)[1]), "+f"((c)[2]), "+f"((c)[3]) \
        : "r"((a)[0]), "r"((a)[1]), "r"((a)[2]), "r"((a)[3]), "r"((b)[0]), "r"((b)[1]))

__device__ __forceinline__ unsigned long long ffma2(unsigned long long a,
                                                    unsigned long long b,
                                                    unsigned long long c) {
    unsigned long long d;
    asm("fma.rn.f32x2 %0, %1, %2, %3;" : "=l"(d) : "l"(a), "l"(b), "l"(c));
    return d;
}
__device__ __forceinline__ unsigned long long dup2(float x) {
    unsigned long long d;
    asm("mov.b64 %0, {%1, %1};" : "=l"(d) : "f"(x));
    return d;
}
__device__ __forceinline__ float2 up2(unsigned long long v) {
    float2 r;
    asm("mov.b64 {%0, %1}, %2;" : "=f"(r.x), "=f"(r.y) : "l"(v));
    return r;
}
__device__ __forceinline__ unsigned long long d2u(double d) {
    return (unsigned long long)__double_as_longlong(d);
}

// ---------------- preds ----------------
__global__ __launch_bounds__(256) void preds_kernel(const float* __restrict__ feat,
                                                    const float* __restrict__ proto) {
    __shared__ float sp[CC][DD];
    int tid = threadIdx.x;
    if (tid < CC) {
        float s = 0.f;
        for (int k = 0; k < DD; k++) { float v = proto[tid * DD + k]; s += v * v; }
        float inv = 1.f / fmaxf(sqrtf(s), 1e-12f);
        for (int k = 0; k < DD; k++) sp[tid][k] = proto[tid * DD + k] * inv;
    }
    __syncthreads();
    int n = blockIdx.x * 256 + tid;
    if (n >= NN) return;
    const float* f = feat + (long long)n * DD;
    float acc[CC];
#pragma unroll
    for (int c = 0; c < CC; c++) acc[c] = 0.f;
#pragma unroll 4
    for (int k = 0; k < DD; k++) {
        float fk = f[k];
#pragma unroll
        for (int c = 0; c < CC; c++) acc[c] += fk * sp[c][k];
    }
    float best = acc[0];
    int bi = 0;
#pragma unroll
    for (int c = 1; c < CC; c++)
        if (acc[c] > best) { best = acc[c]; bi = c; }
    d_preds[n] = bi;
}

// ---------------- mask + per-block count ----------------
__global__ __launch_bounds__(256) void mask_kernel(const float* __restrict__ coords,
                                                   const float* __restrict__ normz,
                                                   const void* __restrict__ nidx) {
    __shared__ int wsum[8];
    int tid = threadIdx.x;
    int n = blockIdx.x * 256 + tid;
    bool mk = false;
    if (n < NN) {
        const int* pw = (const int*)nidx;
        int is64 = 1;
#pragma unroll
        for (int k = 1; k < 40; k += 2) is64 &= (pw[k] == 0);
        int p = d_preds[n];
        const long long* ni64 = (const long long*)nidx;
        const int*       ni32 = (const int*)nidx;
        int cnt = 0;
#pragma unroll
        for (int k = 0; k < KK; k++) {
            long long raw = is64 ? ni64[(long long)n * KK + k]
                                 : (long long)ni32[(long long)n * KK + k];
            unsigned int idx = (unsigned int)raw;
            if (idx >= NN) idx = 0;
            cnt += (d_preds[idx] == p);
        }
        bool cmask = cnt > 16;
        bool plane   = (p == 2) | (p == 3) | (p == 4);
        bool manmade = (p == 5);
        bool other   = (p == 0) | (p == 1) | (p == 6);
        float nz = normz[n];
        float z  = coords[(long long)n * 3 + 2];
        bool ground = plane && (nz > 0.9f) && (z < -10.0f);
        bool g = ground || other || manmade;
        bool m = (manmade && (nz < 0.1f)) || other || plane;
        mk = cmask && g && m;
        d_maskf[n] = mk ? 1.f : 0.f;
    }
    unsigned int b = __ballot_sync(0xffffffffu, mk);
    if ((tid & 31) == 0) wsum[tid >> 5] = __popc(b);
    __syncthreads();
    if (tid == 0) {
        int s = 0;
#pragma unroll
        for (int w = 0; w < 8; w++) s += wsum[w];
        d_bcnt[blockIdx.x] = s;
    }
}

// ---------------- scan ----------------
__global__ __launch_bounds__(512) void scan_kernel() {
    __shared__ int s[NBLK];
    int tid = threadIdx.x;
    if (tid < NBLK) s[tid] = d_bcnt[tid];
    __syncthreads();
    if (tid == 0) {
        int run = 0;
        for (int i = 0; i < NBLK; i++) { int v = s[i]; s[i] = run; run += v; }
        d_nact = run;
        d_nchunk = (run + 63) / 64;
    }
    __syncthreads();
    if (tid < NBLK) d_boff[tid] = s[tid];
}

// ---------------- scatter ----------------
__global__ __launch_bounds__(256) void scatter_kernel() {
    __shared__ int wcnt[8];
    __shared__ int woff[8];
    int tid = threadIdx.x;
    int n = blockIdx.x * 256 + tid;
    bool mk = (n < NN) && (d_maskf[n] != 0.f);
    unsigned int b = __ballot_sync(0xffffffffu, mk);
    int lane = tid & 31, wid = tid >> 5;
    if (lane == 0) wcnt[wid] = __popc(b);
    __syncthreads();
    if (tid == 0) {
        int run = 0;
#pragma unroll
        for (int w = 0; w < 8; w++) { woff[w] = run; run += wcnt[w]; }
    }
    __syncthreads();
    if (mk) {
        int rank = __popc(b & ((1u << lane) - 1u));
        d_active[d_boff[blockIdx.x] + woff[wid] + rank] = n;
    }
}

// ---------------- feath: 128x128 tile, 8x8/thread, fp32 only ----------------
#define FB_STRIDE 132
__global__ __launch_bounds__(256) void feath_kernel(const float* __restrict__ feat,
                                                    const float* __restrict__ w) {
    __shared__ __align__(16) float As[32][FB_STRIDE];
    __shared__ __align__(16) float Bs[32][FB_STRIDE];
    int tid = threadIdx.x;
    int h0 = blockIdx.x * 128;
    int n0 = blockIdx.y * 128;
    int tx = tid & 15, ty = tid >> 4;

    unsigned long long acc[8][4];
#pragma unroll
    for (int r = 0; r < 8; r++)
#pragma unroll
        for (int c = 0; c < 4; c++) acc[r][c] = 0ull;

    for (int k0 = 0; k0 < DD; k0 += 32) {
        for (int i = tid; i < 4096; i += 256) {
            int k = i & 31, m = i >> 5;
            int n = n0 + m;
            As[k][m] = (n < NN) ? feat[(long long)n * DD + k0 + k] : 0.f;
        }
        for (int i = tid; i < 4096; i += 256) {
            int k = i >> 7, m = i & 127;
            Bs[k][m] = w[(k0 + k) * HH + h0 + m];
        }
        __syncthreads();
#pragma unroll
        for (int k = 0; k < 32; k++) {
            float4 a0 = *reinterpret_cast<const float4*>(&As[k][ty * 8]);
            float4 a1 = *reinterpret_cast<const float4*>(&As[k][ty * 8 + 4]);
            double2 b0 = *reinterpret_cast<const double2*>(&Bs[k][tx * 8]);
            double2 b1 = *reinterpret_cast<const double2*>(&Bs[k][tx * 8 + 4]);
            unsigned long long bp0 = d2u(b0.x), bp1 = d2u(b0.y);
            unsigned long long bp2 = d2u(b1.x), bp3 = d2u(b1.y);
            float av[8] = {a0.x, a0.y, a0.z, a0.w, a1.x, a1.y, a1.z, a1.w};
#pragma unroll
            for (int rn = 0; rn < 8; rn++) {
                unsigned long long ap = dup2(av[rn]);
                acc[rn][0] = ffma2(ap, bp0, acc[rn][0]);
                acc[rn][1] = ffma2(ap, bp1, acc[rn][1]);
                acc[rn][2] = ffma2(ap, bp2, acc[rn][2]);
                acc[rn][3] = ffma2(ap, bp3, acc[rn][3]);
            }
        }
        __syncthreads();
    }
#pragma unroll
    for (int rn = 0; rn < 8; rn++) {
        int n = n0 + ty * 8 + rn;
        if (n < NN) {
            float2 f0 = up2(acc[rn][0]);
            float2 f1 = up2(acc[rn][1]);
            float2 f2 = up2(acc[rn][2]);
            float2 f3 = up2(acc[rn][3]);
            float* dst = &d_featH[(long long)n * HH + h0 + tx * 8];
            *reinterpret_cast<float4*>(dst) =
                make_float4(fmaxf(f0.x, 0.f), fmaxf(f0.y, 0.f),
                            fmaxf(f1.x, 0.f), fmaxf(f1.y, 0.f));
            *reinterpret_cast<float4*>(dst + 4) =
                make_float4(fmaxf(f2.x, 0.f), fmaxf(f2.y, 0.f),
                            fmaxf(f3.x, 0.f), fmaxf(f3.y, 0.f));
        }
    }
}

// ---------------- compact ----------------
__global__ __launch_bounds__(256) void compact_kernel() {
    __shared__ float sT[64][65];
    int tid = threadIdx.x;
    int h0 = blockIdx.x * 64;
    int NCH = d_nchunk;
    int nact = d_nact;
    for (int cb = blockIdx.y; cb < NCH; cb += 64) {
        int p0 = cb * 64;
        int pl = tid >> 2, seg = tid & 3;
        int p = p0 + pl;
        int n = (p < nact) ? d_active[p] : -1;
        float4 v0, v1, v2, v3;
        if (n >= 0) {
            const float* src = &d_featH[(long long)n * HH + h0 + seg * 16];
            v0 = *reinterpret_cast<const float4*>(src);
            v1 = *reinterpret_cast<const float4*>(src + 4);
            v2 = *reinterpret_cast<const float4*>(src + 8);
            v3 = *reinterpret_cast<const float4*>(src + 12);
        } else {
            v0 = v1 = v2 = v3 = make_float4(0.f, 0.f, 0.f, 0.f);
        }
        __syncthreads();
        {
            int hb = seg * 16;
            sT[hb + 0][pl] = v0.x;  sT[hb + 1][pl] = v0.y;
            sT[hb + 2][pl] = v0.z;  sT[hb + 3][pl] = v0.w;
            sT[hb + 4][pl] = v1.x;  sT[hb + 5][pl] = v1.y;
            sT[hb + 6][pl] = v1.z;  sT[hb + 7][pl] = v1.w;
            sT[hb + 8][pl] = v2.x;  sT[hb + 9][pl] = v2.y;
            sT[hb + 10][pl] = v2.z; sT[hb + 11][pl] = v2.w;
            sT[hb + 12][pl] = v3.x; sT[hb + 13][pl] = v3.y;
            sT[hb + 14][pl] = v3.z; sT[hb + 15][pl] = v3.w;
        }
        __syncthreads();
        {
            int hrow = tid >> 2, q = tid & 3;
            __align__(16) __nv_bfloat16 hb16[16], lb16[16];
#pragma unroll
            for (int i = 0; i < 16; i++) {
                float v = sT[hrow][q * 16 + i];
                __nv_bfloat16 h = __float2bfloat16(v);
                hb16[i] = h;
                lb16[i] = __float2bfloat16(v - __bfloat162float(h));
            }
            size_t gb = (size_t)(h0 + hrow) * KPAD + p0 + q * 16;
            *reinterpret_cast<uint4*>(&d_Fhi[gb])     = *reinterpret_cast<uint4*>(&hb16[0]);
            *reinterpret_cast<uint4*>(&d_Fhi[gb + 8]) = *reinterpret_cast<uint4*>(&hb16[8]);
            *reinterpret_cast<uint4*>(&d_Flo[gb])     = *reinterpret_cast<uint4*>(&lb16[0]);
            *reinterpret_cast<uint4*>(&d_Flo[gb + 8]) = *reinterpret_cast<uint4*>(&lb16[8]);
        }
    }
}

// ---------------- Gram (dynamic chunk count) ----------------
__global__ __launch_bounds__(1024, 1) void gram_hmma_kernel() {
    extern __shared__ __align__(16) char smg[];
    uint32_t sb = smem_to_u32(smg);
    int tid = threadIdx.x;
    int t = blockIdx.x, sp = blockIdx.y;
    int bi = 0;
    while ((bi + 1) * (bi + 2) / 2 <= t) bi++;
    int bj = t - bi * (bi + 1) / 2;
    int h10 = bi * 128, h20 = bj * 128;

    int NCH = d_nchunk;
    int cps = (NCH + GSPLIT - 1) / GSPLIT;
    int c0 = sp * cps;
    int cnt = min(c0 + cps, NCH) - c0;
    float* out = &d_Spart[(size_t)(sp * NTRI + t) * 128 * 128];

    if (cnt <= 0) {
        float4 z = make_float4(0.f, 0.f, 0.f, 0.f);
        for (int i = tid; i < 128 * 128 / 4; i += 1024)
            *reinterpret_cast<float4*>(&out[i * 4]) = z;
        return;
    }

    int lrow = tid >> 3, lseg = tid & 7;
    size_t kstart = (size_t)c0 * 64 + lseg * 8;
    const __nv_bfloat16* pAh = d_Fhi + (size_t)(h10 + lrow) * KPAD + kstart;
    const __nv_bfloat16* pAl = d_Flo + (size_t)(h10 + lrow) * KPAD + kstart;
    const __nv_bfloat16* pBh = d_Fhi + (size_t)(h20 + lrow) * KPAD + kstart;
    const __nv_bfloat16* pBl = d_Flo + (size_t)(h20 + lrow) * KPAD + kstart;
    uint32_t ldst = sb + lrow * GS_ROWB + lseg * 16;

    int wid = tid >> 5, lane = tid & 31;
    int mbase = (wid >> 2) * 16, nbase = (wid & 3) * 32;
    int arow = (lane & 7) + ((lane >> 3) & 1) * 8;
    int acol = ((lane >> 4) & 1) * 8;
    int brow = (lane & 7) + ((lane >> 4) & 1) * 8;
    int bcol = ((lane >> 3) & 1) * 8;
    uint32_t aoff = (uint32_t)(((mbase + arow) * 72 + acol) * 2);
    uint32_t boff[2];
#pragma unroll
    for (int nj = 0; nj < 2; nj++)
        boff[nj] = (uint32_t)(((nbase + nj * 16 + brow) * 72 + bcol) * 2);

    float acc[4][4];
#pragma unroll
    for (int b = 0; b < 4; b++)
#pragma unroll
        for (int c = 0; c < 4; c++) acc[b][c] = 0.f;

    CP_ASYNC16(ldst + 0 * GS_TILE, pAh);
    CP_ASYNC16(ldst + 1 * GS_TILE, pAl);
    CP_ASYNC16(ldst + 2 * GS_TILE, pBh);
    CP_ASYNC16(ldst + 3 * GS_TILE, pBl);
    CP_COMMIT();

    for (int c = 0; c < cnt; c++) {
        if (c + 1 < cnt) {
            uint32_t base = ldst + ((c + 1) & 1) * GS_STAGE;
            size_t ko = (size_t)(c + 1) * 64;
            CP_ASYNC16(base + 0 * GS_TILE, pAh + ko);
            CP_ASYNC16(base + 1 * GS_TILE, pAl + ko);
            CP_ASYNC16(base + 2 * GS_TILE, pBh + ko);
            CP_ASYNC16(base + 3 * GS_TILE, pBl + ko);
            CP_COMMIT();
            CP_WAIT1();
        } else {
            CP_WAIT0();
        }
        __syncthreads();
        uint32_t stg = sb + (c & 1) * GS_STAGE;
#pragma unroll
        for (int ks = 0; ks < 4; ks++) {
            uint32_t kb = ks * 32;
            uint32_t ah[4], al[4], bh[4][2], bl[4][2];
            LDSM4(ah, stg + 0 * GS_TILE + aoff + kb);
#pragma unroll
            for (int nj = 0; nj < 2; nj++) {
                uint32_t r[4];
                LDSM4(r, stg + 2 * GS_TILE + boff[nj] + kb);
                bh[nj * 2][0] = r[0]; bh[nj * 2][1] = r[1];
                bh[nj * 2 + 1][0] = r[2]; bh[nj * 2 + 1][1] = r[3];
            }
#pragma unroll
            for (int nj = 0; nj < 4; nj++) MMA16816(acc[nj], ah, bh[nj]);
#pragma unroll
            for (int nj = 0; nj < 2; nj++) {
                uint32_t r[4];
                LDSM4(r, stg + 3 * GS_TILE + boff[nj] + kb);
                bl[nj * 2][0] = r[0]; bl[nj * 2][1] = r[1];
                bl[nj * 2 + 1][0] = r[2]; bl[nj * 2 + 1][1] = r[3];
            }
#pragma unroll
            for (int nj = 0; nj < 4; nj++) MMA16816(acc[nj], ah, bl[nj]);
            LDSM4(al, stg + 1 * GS_TILE + aoff + kb);
#pragma unroll
            for (int nj = 0; nj < 4; nj++) MMA16816(acc[nj], al, bh[nj]);
        }
        __syncthreads();
    }

    int g = lane >> 2, q = lane & 3;
#pragma unroll
    for (int nj = 0; nj < 4; nj++) {
        int r0 = mbase + g;
        int cc = nbase + nj * 8 + q * 2;
        *reinterpret_cast<float2*>(&out[r0 * 128 + cc]) =
            make_float2(acc[nj][0], acc[nj][1]);
        *reinterpret_cast<float2*>(&out[(r0 + 8) * 128 + cc]) =
            make_float2(acc[nj][2], acc[nj][3]);
    }
}

// ---------------- reduce split-K partials ----------------
__global__ __launch_bounds__(256) void greduce_kernel() {
    int t = blockIdx.x;
    int bi = 0;
    while ((bi + 1) * (bi + 2) / 2 <= t) bi++;
    int bj = t - bi * (bi + 1) / 2;
    for (int i = threadIdx.x; i < 128 * 128 / 4; i += 256) {
        float4 s = make_float4(0.f, 0.f, 0.f, 0.f);
#pragma unroll
        for (int sp = 0; sp < GSPLIT; sp++) {
            float4 v = *reinterpret_cast<const float4*>(
                &d_Spart[(size_t)(sp * NTRI + t) * 128 * 128 + i * 4]);
            s.x += v.x; s.y += v.y; s.z += v.z; s.w += v.w;
        }
        int r = (i * 4) >> 7, c = (i * 4) & 127;
        *reinterpret_cast<float4*>(&d_Gn[(bi * 128 + r) * HH + bj * 128 + c]) = s;
    }
}

// ---------------- Qn partials over active list ----------------
__global__ __launch_bounds__(256) void qpart_kernel() {
    int h = blockIdx.x * 256 + threadIdx.x;
    int chunk = blockIdx.y;
    int nact = d_nact;
    int stride = (nact + NCHUNK - 1) / NCHUNK;
    int p0 = chunk * stride;
    int p1 = min(p0 + stride, nact);
    float a0 = 0, a1 = 0, a2 = 0, a3 = 0, a4 = 0, a5 = 0, a6 = 0;
    for (int p = p0; p < p1; p++) {
        int n = d_active[p];
        float v = d_featH[(long long)n * HH + h];
        int pr = d_preds[n];
        a0 += (pr == 0) ? v : 0.f;
        a1 += (pr == 1) ? v : 0.f;
        a2 += (pr == 2) ? v : 0.f;
        a3 += (pr == 3) ? v : 0.f;
        a4 += (pr == 4) ? v : 0.f;
        a5 += (pr == 5) ? v : 0.f;
        a6 += (pr == 6) ? v : 0.f;
    }
    int o = (chunk * HH + h) * CC;
    d_Qpart[o + 0] = a0; d_Qpart[o + 1] = a1; d_Qpart[o + 2] = a2; d_Qpart[o + 3] = a3;
    d_Qpart[o + 4] = a4; d_Qpart[o + 5] = a5; d_Qpart[o + 6] = a6;
}

__global__ void qreduce_kernel(const float* __restrict__ Qin) {
    int idx = blockIdx.x * 256 + threadIdx.x;
    if (idx >= HH * CC) return;
    float s = Qin[idx];
    for (int ch = 0; ch < NCHUNK; ch++) s += d_Qpart[ch * HH * CC + idx];
    d_Qn[idx] = s;
}

// ---------------- mirror + Gin + ridge ----------------
__global__ void convm_kernel(const float* __restrict__ Gin) {
    int idx = blockIdx.x * 256 + threadIdx.x;
    int i = idx >> 10, j = idx & 1023;
    float v = (i >= j) ? d_Gn[i * HH + j] : d_Gn[j * HH + i];
    float a = v + Gin[idx] + ((i == j) ? 100.0f : 0.0f);
    d_GA[idx] = a;
    d_Gf[idx] = a;
}

// ================= fused Cholesky (warp-diag) + solves =================
__device__ __forceinline__ void gbar() {
    __threadfence();
    __syncthreads();
    if (threadIdx.x == 0) {
        unsigned int gen = atomicAdd(&g_gen, 0u);
        if (atomicAdd(&g_cnt, 1u) == NB - 1) {
            atomicExch(&g_cnt, 0u);
            __threadfence();
            atomicAdd(&g_gen, 1u);
        } else {
            while (atomicAdd(&g_gen, 0u) == gen) { __nanosleep(64); }
        }
        __threadfence();
    }
    __syncthreads();
}

// block-0 triangular solve using smem ys (1024x7) and Ld (64x65)
__device__ void solve_block0(float* csm, const float* b, int mode) {
    float* ys = csm;              // 7168 floats
    float* Ld = csm + HH * CC;    // 64*65 = 4160 floats
    __shared__ float di64[64];
    int tid = threadIdx.x;
    int lane = tid & 31, wid = tid >> 5;

    for (int i = tid; i < HH * CC; i += 1024) ys[i] = b[i];
    __syncthreads();

    // forward: L y = b
    for (int jb = 0; jb < HH; jb += 64) {
        for (int i = tid; i < 64 * 64; i += 1024)
            Ld[(i >> 6) * 65 + (i & 63)] = d_Gf[(jb + (i >> 6)) * HH + jb + (i & 63)];
        if (tid < 64) di64[tid] = d_dinvf[jb + tid];
        __syncthreads();
        if (wid == 0) {
            for (int j = 0; j < 64; j++) {
                if (lane < CC) ys[(jb + j) * CC + lane] *= di64[j];
                __syncwarp();
                for (int rr = j + 1 + lane; rr < 64; rr += 32) {
                    float l = Ld[rr * 65 + j];
#pragma unroll
                    for (int c = 0; c < CC; c++)
                        ys[(jb + rr) * CC + c] -= l * ys[(jb + j) * CC + c];
                }
                __syncwarp();
            }
        }
        __syncthreads();
        // bulk update rows below (<= 960 rows, one per thread)
        int r = jb + 64 + tid;
        if (r < HH) {
            float acc[CC];
#pragma unroll
            for (int c = 0; c < CC; c++) acc[c] = 0.f;
            const float* lrow = &d_Gf[(size_t)r * HH + jb];
#pragma unroll 8
            for (int t = 0; t < 64; t++) {
                float l = lrow[t];
#pragma unroll
                for (int c = 0; c < CC; c++) acc[c] += l * ys[(jb + t) * CC + c];
            }
#pragma unroll
            for (int c = 0; c < CC; c++) ys[r * CC + c] -= acc[c];
        }
        __syncthreads();
    }

    // backward: L^T x = y
    for (int jb = HH - 64; jb >= 0; jb -= 64) {
        for (int i = tid; i < 64 * 64; i += 1024)
            Ld[(i >> 6) * 65 + (i & 63)] = d_Gf[(jb + (i >> 6)) * HH + jb + (i & 63)];
        if (tid < 64) di64[tid] = d_dinvf[jb + tid];
        __syncthreads();
        if (wid == 0) {
            for (int j = 63; j >= 0; j--) {
                if (lane < CC) ys[(jb + j) * CC + lane] *= di64[j];
                __syncwarp();
                for (int rr = lane; rr < j; rr += 32) {
                    float l = Ld[j * 65 + rr];      // L[j][rr] = L^T[rr][j]
#pragma unroll
                    for (int c = 0; c < CC; c++)
                        ys[(jb + rr) * CC + c] -= l * ys[(jb + j) * CC + c];
                }
                __syncwarp();
            }
        }
        __syncthreads();
        // bulk: rows r < jb, coalesced column reads
        int r = tid;
        if (r < jb) {
            float acc[CC];
#pragma unroll
            for (int c = 0; c < CC; c++) acc[c] = 0.f;
#pragma unroll 8
            for (int t = 0; t < 64; t++) {
                float l = d_Gf[(size_t)(jb + t) * HH + r];
#pragma unroll
                for (int c = 0; c < CC; c++) acc[c] += l * ys[(jb + t) * CC + c];
            }
#pragma unroll
            for (int c = 0; c < CC; c++) ys[r * CC + c] -= acc[c];
        }
        __syncthreads();
    }

    if (mode == 0) {
        for (int i = tid; i < HH * CC; i += 1024) d_wo[i] = ys[i];
    } else {
        for (int i = tid; i < HH * CC; i += 1024) d_wo[i] += ys[i];
    }
    __syncthreads();
}

__global__ __launch_bounds__(1024, 1) void chol_fused() {
    extern __shared__ float csm[];       // CSM_FLOATS
    __shared__ float di_s[PB];

    int tid = threadIdx.x;
    int bid = blockIdx.x;
    int lane = tid & 31, wid = tid >> 5;

    // ---------- factorization: 8 rounds of 128-panel ----------
    for (int kb = 0; kb < HH / PB; kb++) {
        int off = kb * PB;
        // phase A: potf2 128x128 in smem by block 0 (warp-diag + block updates)
        if (bid == 0) {
            float* S = csm;              // [128][132]
            for (int i = tid; i < PB * PB; i += 1024)
                S[(i >> 7) * 132 + (i & 127)] = d_Gf[(off + (i >> 7)) * HH + off + (i & 127)];
            __syncthreads();
            for (int sub = 0; sub < 4; sub++) {
                int s0 = sub * 32;
                // warp 0 factors 32x32 diagonal block
                if (wid == 0) {
                    int r = lane;
                    for (int j = 0; j < 32; j++) {
                        if (lane == 0) {
                            float d = sqrtf(fmaxf(S[(s0 + j) * 132 + s0 + j], 1e-20f));
                            S[(s0 + j) * 132 + s0 + j] = d;
                            di_s[s0 + j] = 1.f / d;
                        }
                        __syncwarp();
                        float di = di_s[s0 + j];
                        if (r > j) S[(s0 + r) * 132 + s0 + j] *= di;
                        __syncwarp();
                        if (r > j) {
                            float ljr = S[(s0 + r) * 132 + s0 + j];
                            for (int k = j + 1; k <= r; k++)
                                S[(s0 + r) * 132 + s0 + k] -= ljr * S[(s0 + k) * 132 + s0 + j];
                        }
                        __syncwarp();
                    }
                }
                __syncthreads();
                // panel trsm: rows below diag block (warp-per-row, shfl substitution)
                int nrw = PB - (s0 + 32);
                if (nrw > 0) {
                    for (int rw = wid; rw < nrw; rw += 32) {
                        int rr = s0 + 32 + rw;
                        float x = S[rr * 132 + s0 + lane];
#pragma unroll
                        for (int j = 0; j < 32; j++) {
                            float xj = __shfl_sync(0xffffffffu, x * di_s[s0 + j], j);
                            if (lane == j) x = xj;
                            if (lane > j) x -= xj * S[(s0 + lane) * 132 + s0 + j];
                        }
                        S[rr * 132 + s0 + lane] = x;
                    }
                    __syncthreads();
                    // rank-32 trailing update (lower region)
                    int base2 = s0 + 32;
                    int msz = PB - base2;
                    for (int e = tid; e < msz * msz; e += 1024) {
                        int r2 = base2 + e / msz, k2 = base2 + e % msz;
                        if (k2 <= r2) {
                            float s = 0.f;
#pragma unroll
                            for (int t = 0; t < 32; t++)
                                s += S[r2 * 132 + s0 + t] * S[k2 * 132 + s0 + t];
                            S[r2 * 132 + k2] -= s;
                        }
                    }
                    __syncthreads();
                }
            }
            // write back lower + dinv
            for (int i = tid; i < PB * PB; i += 1024) {
                int r = i >> 7, c = i & 127;
                if (r >= c) d_Gf[(off + r) * HH + off + c] = S[r * 132 + c];
            }
            if (tid < PB) d_dinvf[off + tid] = di_s[tid];
            __syncthreads();
        }
        gbar();

        int base = off + PB;
        int rows = HH - base;
        if (rows > 0) {
            // phase B: trsm vs 128-panel, warp-per-row, lane owns cols 4l..4l+3
            float* L = csm;              // [128][132]
            for (int i = tid; i < PB * PB; i += 1024)
                L[(i >> 7) * 132 + (i & 127)] = d_Gf[(off + (i >> 7)) * HH + off + (i & 127)];
            if (tid < PB) di_s[tid] = d_dinvf[off + tid];
            __syncthreads();
            int gw = bid * 32 + wid;
            if (gw < rows) {
                int r = base + gw;
                float* a = &d_Gf[r * HH + off];
                int c0 = lane * 4;
                float x0 = a[c0], x1 = a[c0 + 1], x2 = a[c0 + 2], x3 = a[c0 + 3];
#pragma unroll
                for (int j = 0; j < PB; j++) {
                    int owner = j >> 2;
                    int qj = j & 3;
                    float xown = (qj == 0) ? x0 : (qj == 1) ? x1 : (qj == 2) ? x2 : x3;
                    float xj = __shfl_sync(0xffffffffu, xown * di_s[j], owner);
                    if (lane == owner) {
                        if (qj == 0) x0 = xj; else if (qj == 1) x1 = xj;
                        else if (qj == 2) x2 = xj; else x3 = xj;
                    }
                    if (c0 + 0 > j) x0 -= xj * L[(c0 + 0) * 132 + j];
                    if (c0 + 1 > j) x1 -= xj * L[(c0 + 1) * 132 + j];
                    if (c0 + 2 > j) x2 -= xj * L[(c0 + 2) * 132 + j];
                    if (c0 + 3 > j) x3 -= xj * L[(c0 + 3) * 132 + j];
                }
                a[c0] = x0; a[c0 + 1] = x1; a[c0 + 2] = x2; a[c0 + 3] = x3;
            }
            gbar();

            // phase C: syrk K=128 (two K=64 passes), 64x64 lower tiles
            float* Li = csm;
            float* Lj = csm + 64 * 65;
            int T = rows / 64;
            int ntiles = T * (T + 1) / 2;
            for (int idx = bid; idx < ntiles; idx += NB) {
                int ti = 0;
                while ((ti + 1) * (ti + 2) / 2 <= idx) ti++;
                int tj = idx - ti * (ti + 1) / 2;
                int i0 = base + ti * 64, j0 = base + tj * 64;
                int tx = tid & 63, tg = tid >> 6;
                float acc[4] = {0.f, 0.f, 0.f, 0.f};
#pragma unroll
                for (int koff = 0; koff < PB; koff += 64) {
                    __syncthreads();
                    for (int i = tid; i < 64 * 64; i += 1024) {
                        Li[(i >> 6) * 65 + (i & 63)] =
                            d_Gf[(i0 + (i >> 6)) * HH + off + koff + (i & 63)];
                        Lj[(i >> 6) * 65 + (i & 63)] =
                            d_Gf[(j0 + (i >> 6)) * HH + off + koff + (i & 63)];
                    }
                    __syncthreads();
                    for (int t = 0; t < 64; t++) {
                        float bj = Lj[tx * 65 + t];
#pragma unroll
                        for (int s = 0; s < 4; s++) acc[s] += Li[(tg + s * 16) * 65 + t] * bj;
                    }
                }
#pragma unroll
                for (int s = 0; s < 4; s++)
                    d_Gf[(i0 + tg + s * 16) * HH + j0 + tx] -= acc[s];
            }
            gbar();
        } else {
            gbar();
            gbar();
        }
    }

    // ---------- solve mode 0 ----------
    if (bid == 0) solve_block0(csm, d_Qn, 0);
    gbar();

    // ---------- residual (all blocks, warp per row) ----------
    {
        float* sw = csm;
        for (int i = tid; i < HH * CC; i += 1024) sw[i] = d_wo[i];
        __syncthreads();
        int row = bid * 32 + wid;
        float s[CC], comp[CC];
#pragma unroll
        for (int c = 0; c < CC; c++) {
            s[c] = (lane == 0) ? d_Qn[row * CC + c] : 0.f;
            comp[c] = 0.f;
        }
        const float* arow = &d_GA[row * HH];
        for (int j = lane; j < HH; j += 32) {
            float na = -arow[j];
#pragma unroll
            for (int c = 0; c < CC; c++) {
                float w = sw[j * CC + c];
                float p = na * w;
                float e = fmaf(na, w, -p);
                float t = s[c] + p;
                float bb = t - s[c];
                float err = (s[c] - (t - bb)) + (p - bb);
                s[c] = t;
                comp[c] += err + e;
            }
        }
#pragma unroll
        for (int c = 0; c < CC; c++) {
#pragma unroll
            for (int off2 = 16; off2 > 0; off2 >>= 1) {
                float s2 = __shfl_xor_sync(0xffffffffu, s[c], off2);
                float c2 = __shfl_xor_sync(0xffffffffu, comp[c], off2);
                float t = s[c] + s2;
                float bb = t - s[c];
                float err = (s[c] - (t - bb)) + (s2 - bb);
                s[c] = t;
                comp[c] += c2 + err;
            }
        }
        if (lane == 0) {
#pragma unroll
            for (int c = 0; c < CC; c++) d_res[row * CC + c] = s[c] + comp[c];
        }
    }
    gbar();

    // ---------- solve mode 1: wo += L^-T L^-1 res ----------
    if (bid == 0) solve_block0(csm, d_res, 1);
}

// ---------------- final ----------------
__global__ __launch_bounds__(256) void final_kernel(float* __restrict__ out) {
    __shared__ float sw[HH * CC];
    int tid = threadIdx.x;
    for (int i = tid; i < HH * CC; i += 256) sw[i] = d_wo[i];
    __syncthreads();
    int warp = tid >> 5, lane = tid & 31;
    int n = blockIdx.x * 8 + warp;
    if (n >= NN) return;
    const float* a = &d_featH[(long long)n * HH];
    float acc[CC];
#pragma unroll
    for (int c = 0; c < CC; c++) acc[c] = 0.f;
#pragma unroll
    for (int h = lane; h < HH; h += 32) {
        float v = a[h];
#pragma unroll
        for (int c = 0; c < CC; c++) acc[c] += v * sw[h * CC + c];
    }
#pragma unroll
    for (int c = 0; c < CC; c++) {
#pragma unroll
        for (int off = 16; off > 0; off >>= 1)
            acc[c] += __shfl_xor_sync(0xffffffffu, acc[c], off);
    }
    if (lane == 0) {
#pragma unroll
        for (int c = 0; c < CC; c++) out[(long long)n * CC + c] = acc[c];
    }
}

// ---------------- launcher ----------------
extern "C" void kernel_launch(void* const* d_in, const int* in_sizes, int n_in,
                              void* d_out, int out_size) {
    const float* feat   = (const float*)d_in[0];
    const float* proto  = (const float*)d_in[1];
    const float* wrand  = (const float*)d_in[2];
    const float* Qin    = (const float*)d_in[3];
    const float* Gin    = (const float*)d_in[4];
    const float* coords = (const float*)d_in[5];
    const float* normz  = (const float*)d_in[6];
    const void*  nidx   = (const void*)d_in[7];
    float* out = (float*)d_out;

    cudaFuncSetAttribute(gram_hmma_kernel,
                         cudaFuncAttributeMaxDynamicSharedMemorySize, GS_TOTAL);
    cudaFuncSetAttribute(chol_fused,
                         cudaFuncAttributeMaxDynamicSharedMemorySize, CSM_FLOATS * 4);

    preds_kernel<<<(NN + 255) / 256, 256>>>(feat, proto);                  // 0
    mask_kernel<<<NBLK, 256>>>(coords, normz, nidx);                       // 1
    scan_kernel<<<1, 512>>>();                                             // 2
    feath_kernel<<<dim3(HH / 128, (NN + 127) / 128), 256>>>(feat, wrand);  // 3 <- ncu slot
    scatter_kernel<<<NBLK, 256>>>();                                       // 4
    compact_kernel<<<dim3(HH / 64, 64), 256>>>();                          // 5
    gram_hmma_kernel<<<dim3(NTRI, GSPLIT), 1024, GS_TOTAL>>>();            // 6
    greduce_kernel<<<NTRI, 256>>>();                                       // 7
    qpart_kernel<<<dim3(HH / 256, NCHUNK), 256>>>();                       // 8
    qreduce_kernel<<<(HH * CC + 255) / 256, 256>>>(Qin);                   // 9
    convm_kernel<<<(HH * HH) / 256, 256>>>(Gin);                           // 10
    chol_fused<<<NB, 1024, CSM_FLOATS * 4>>>();                            // 11
    final_kernel<<<(NN + 7) / 8, 256>>>(out);                              // 12
}